// round 5
// baseline (speedup 1.0000x reference)
#include <cuda_runtime.h>
#include <cuda_bf16.h>
#include <math.h>

#define BB 2
#define SS 2048
#define HID 1024
#define NH 16
#define DK 64
#define MM (BB*SS)   // 4096

// ---------------------------------------------------------------------------
// Scratch
// ---------------------------------------------------------------------------
__device__ float g_q[BB*NH*SS*DK];   // [b,h,s,d]
__device__ float g_k[BB*NH*SS*DK];
__device__ float g_v[BB*NH*SS*DK];
__device__ float g_x[BB*SS*HID];     // attention output [b,s,hid]

// ---------------------------------------------------------------------------
// tf32 helpers
// ---------------------------------------------------------------------------
__device__ __forceinline__ unsigned f2tf(float x) {
    unsigned u;
    asm("cvt.rna.tf32.f32 %0, %1;" : "=r"(u) : "f"(x));
    return u;
}

__device__ __forceinline__ void mma_tf32(float& c0, float& c1, float& c2, float& c3,
                                         unsigned a0, unsigned a1, unsigned a2, unsigned a3,
                                         unsigned b0, unsigned b1) {
    asm volatile(
        "mma.sync.aligned.m16n8k8.row.col.f32.tf32.tf32.f32 "
        "{%0,%1,%2,%3},{%4,%5,%6,%7},{%8,%9},{%0,%1,%2,%3};"
        : "+f"(c0), "+f"(c1), "+f"(c2), "+f"(c3)
        : "r"(a0), "r"(a1), "r"(a2), "r"(a3), "r"(b0), "r"(b1));
}

// ---------------------------------------------------------------------------
// GEMM core: out = A[M,1024] @ W[1024,1024]^T + bias, tf32, double-buffered.
// BM=128 BN=128 BK=16, 8 warps, warp tile 64x32. One sync per k-tile;
// next tile's LDGs issued right after STS so latency hides behind 32 MMAs.
// ---------------------------------------------------------------------------
__device__ __forceinline__ void gemm_core(
    const float* __restrict__ A,
    const float* __restrict__ W,
    const float* __restrict__ bias,
    const float* __restrict__ rowscale,
    float* __restrict__ out,
    int transpose_out,
    unsigned (*At)[16][132],
    unsigned (*Bt)[16][132],
    int bm0, int bn0)
{
    const int tid   = threadIdx.x;
    const int warp  = tid >> 5;
    const int lane  = tid & 31;
    const int g     = lane >> 2;
    const int q     = lane & 3;
    const int warpM = warp >> 2;
    const int warpN = warp & 3;

    const int lr = tid >> 1;
    const int lk = (tid & 1) << 3;

    float ascale = 1.0f;
    if (rowscale) ascale = 1.0f + rowscale[bm0 + lr];

    const float* Ap = A + (size_t)(bm0 + lr) * 1024 + lk;
    const float* Wp = W + (size_t)(bn0 + lr) * 1024 + lk;

    float acc[4][4][4];
    #pragma unroll
    for (int mt = 0; mt < 4; mt++)
        #pragma unroll
        for (int nt = 0; nt < 4; nt++)
            #pragma unroll
            for (int i = 0; i < 4; i++) acc[mt][nt][i] = 0.0f;

    // prefetch k-tile 0
    float4 av0 = *(const float4*)(Ap);
    float4 av1 = *(const float4*)(Ap + 4);
    float4 wv0 = *(const float4*)(Wp);
    float4 wv1 = *(const float4*)(Wp + 4);

    for (int kt = 0; kt < 64; kt++) {
        const int buf = kt & 1;
        // stage current tile (consumes prefetch regs)
        At[buf][lk + 0][lr] = f2tf(av0.x * ascale);
        At[buf][lk + 1][lr] = f2tf(av0.y * ascale);
        At[buf][lk + 2][lr] = f2tf(av0.z * ascale);
        At[buf][lk + 3][lr] = f2tf(av0.w * ascale);
        At[buf][lk + 4][lr] = f2tf(av1.x * ascale);
        At[buf][lk + 5][lr] = f2tf(av1.y * ascale);
        At[buf][lk + 6][lr] = f2tf(av1.z * ascale);
        At[buf][lk + 7][lr] = f2tf(av1.w * ascale);
        Bt[buf][lk + 0][lr] = f2tf(wv0.x);
        Bt[buf][lk + 1][lr] = f2tf(wv0.y);
        Bt[buf][lk + 2][lr] = f2tf(wv0.z);
        Bt[buf][lk + 3][lr] = f2tf(wv0.w);
        Bt[buf][lk + 4][lr] = f2tf(wv1.x);
        Bt[buf][lk + 5][lr] = f2tf(wv1.y);
        Bt[buf][lk + 6][lr] = f2tf(wv1.z);
        Bt[buf][lk + 7][lr] = f2tf(wv1.w);

        // issue next tile's loads (latency hidden behind compute below)
        if (kt < 63) {
            const float* Ap2 = Ap + (kt + 1) * 16;
            const float* Wp2 = Wp + (kt + 1) * 16;
            av0 = *(const float4*)(Ap2);
            av1 = *(const float4*)(Ap2 + 4);
            wv0 = *(const float4*)(Wp2);
            wv1 = *(const float4*)(Wp2 + 4);
        }

        __syncthreads();

        #pragma unroll
        for (int kk = 0; kk < 16; kk += 8) {
            unsigned af[4][4];
            #pragma unroll
            for (int mt = 0; mt < 4; mt++) {
                int r = warpM * 64 + mt * 16 + g;
                af[mt][0] = At[buf][kk + q][r];
                af[mt][1] = At[buf][kk + q][r + 8];
                af[mt][2] = At[buf][kk + 4 + q][r];
                af[mt][3] = At[buf][kk + 4 + q][r + 8];
            }
            unsigned bf[4][2];
            #pragma unroll
            for (int nt = 0; nt < 4; nt++) {
                int n = warpN * 32 + nt * 8 + g;
                bf[nt][0] = Bt[buf][kk + q][n];
                bf[nt][1] = Bt[buf][kk + 4 + q][n];
            }
            #pragma unroll
            for (int mt = 0; mt < 4; mt++)
                #pragma unroll
                for (int nt = 0; nt < 4; nt++)
                    mma_tf32(acc[mt][nt][0], acc[mt][nt][1], acc[mt][nt][2], acc[mt][nt][3],
                             af[mt][0], af[mt][1], af[mt][2], af[mt][3],
                             bf[nt][0], bf[nt][1]);
        }
        __syncthreads();
    }

    #pragma unroll
    for (int mt = 0; mt < 4; mt++) {
        #pragma unroll
        for (int nt = 0; nt < 4; nt++) {
            int col = bn0 + warpN * 32 + nt * 8 + 2 * q;
            float b0 = bias[col], b1 = bias[col + 1];
            #pragma unroll
            for (int half = 0; half < 2; half++) {
                int row = bm0 + warpM * 64 + mt * 16 + g + half * 8;
                float2 v;
                v.x = acc[mt][nt][half * 2 + 0] + b0;
                v.y = acc[mt][nt][half * 2 + 1] + b1;
                if (transpose_out) {
                    int bb = row >> 11, ss = row & 2047;
                    int hh = col >> 6, dd = col & 63;
                    *(float2*)&out[(((size_t)bb * NH + hh) * SS + ss) * DK + dd] = v;
                } else {
                    *(float2*)&out[(size_t)row * HID + col] = v;
                }
            }
        }
    }
}

// NOTE on the single sync after compute: with double buffering, the next
// iteration's STS targets buf^1 which no warp is reading; the trailing sync
// prevents iteration kt+2's STS to buf from racing a slow warp's compute(kt).
// Keeping both syncs is the safe form; the compute stage is long enough that
// the second sync is nearly free.

struct QKVArgs {
    const float* q; const float* k; const float* v;
    const float* wq; const float* wk; const float* wv;
    const float* bq; const float* bk; const float* bv;
    const float* bias;     // rowscale for k,v
    float* oq; float* ok; float* ov;
};

__global__ void __launch_bounds__(256)
qkv_gemm_tf32(QKVArgs args)
{
    __shared__ unsigned At[2][16][132];
    __shared__ unsigned Bt[2][16][132];
    const int z = blockIdx.z;
    const float* A  = (z == 0) ? args.q  : (z == 1) ? args.k  : args.v;
    const float* W  = (z == 0) ? args.wq : (z == 1) ? args.wk : args.wv;
    const float* bb = (z == 0) ? args.bq : (z == 1) ? args.bk : args.bv;
    const float* rs = (z == 0) ? (const float*)nullptr : args.bias;
    float* out      = (z == 0) ? args.oq : (z == 1) ? args.ok : args.ov;
    gemm_core(A, W, bb, rs, out, 1, At, Bt,
              blockIdx.y * 128, blockIdx.x * 128);
}

__global__ void __launch_bounds__(256)
out_gemm_tf32(const float* __restrict__ A,
              const float* __restrict__ W,
              const float* __restrict__ bias,
              float* __restrict__ out)
{
    __shared__ unsigned At[2][16][132];
    __shared__ unsigned Bt[2][16][132];
    gemm_core(A, W, bias, nullptr, out, 0, At, Bt,
              blockIdx.y * 128, blockIdx.x * 128);
}

// ---------------------------------------------------------------------------
// Flash attention, tf32 mma, 4 warps, warp tile m32 x n64. (unchanged R4)
// ---------------------------------------------------------------------------
#define QTS 136
#define KTS 68
#define VTS 72
#define PTS 68
#define ATT_SMEM ((64*QTS + 64*KTS + 64*VTS + 128*PTS + 64) * 4)

__global__ void __launch_bounds__(128)
attn_tf32(const int* __restrict__ mask)
{
    extern __shared__ unsigned sm[];
    unsigned* Qt = sm;                       // [64][136]
    unsigned* Kt = Qt + 64 * QTS;            // [64][68]
    unsigned* Vt = Kt + 64 * KTS;            // [64][72]
    unsigned* Ps = Vt + 64 * VTS;            // [128][68]
    float* maskF = (float*)(Ps + 128 * PTS); // [64]

    const int tid  = threadIdx.x;
    const int warp = tid >> 5;
    const int lane = tid & 31;
    const int g    = lane >> 2;
    const int q    = lane & 3;
    const int rb   = warp * 32;

    const int bh = blockIdx.y;
    const int b  = bh >> 4;
    const int h  = bh & 15;
    const int q0 = blockIdx.x * 128;

    const float* qptr = g_q + ((size_t)bh * SS + q0) * DK;
    for (int e = tid; e < 128 * 16; e += 128) {
        int r  = e >> 4;
        int d4 = (e & 15) << 2;
        float4 v = *(const float4*)(qptr + (size_t)r * DK + d4);
        Qt[(d4 + 0) * QTS + r] = f2tf(v.x * 0.125f);
        Qt[(d4 + 1) * QTS + r] = f2tf(v.y * 0.125f);
        Qt[(d4 + 2) * QTS + r] = f2tf(v.z * 0.125f);
        Qt[(d4 + 3) * QTS + r] = f2tf(v.w * 0.125f);
    }

    float o[2][8][4];
    #pragma unroll
    for (int f = 0; f < 2; f++)
        #pragma unroll
        for (int nt = 0; nt < 8; nt++)
            #pragma unroll
            for (int i = 0; i < 4; i++) o[f][nt][i] = 0.0f;
    float mrow[4] = {-1e30f, -1e30f, -1e30f, -1e30f};
    float lrow[4] = {0.0f, 0.0f, 0.0f, 0.0f};

    for (int kt = 0; kt < SS / 64; kt++) {
        __syncthreads();

        const float* kp = g_k + ((size_t)bh * SS + kt * 64) * DK;
        const float* vp = g_v + ((size_t)bh * SS + kt * 64) * DK;
        for (int e = tid; e < 64 * 16; e += 128) {
            int c  = e >> 4;
            int d4 = (e & 15) << 2;
            float4 kv = *(const float4*)(kp + (size_t)c * DK + d4);
            uint4 ku = make_uint4(f2tf(kv.x), f2tf(kv.y), f2tf(kv.z), f2tf(kv.w));
            *(uint4*)&Kt[c * KTS + d4] = ku;
            float4 vv = *(const float4*)(vp + (size_t)c * DK + d4);
            uint4 vu = make_uint4(f2tf(vv.x), f2tf(vv.y), f2tf(vv.z), f2tf(vv.w));
            *(uint4*)&Vt[c * VTS + d4] = vu;
        }
        if (tid < 64)
            maskF[tid] = (mask[b * SS + kt * 64 + tid] == 0) ? 0.0f : 1.0f;
        __syncthreads();

        float s[2][8][4];
        #pragma unroll
        for (int f = 0; f < 2; f++)
            #pragma unroll
            for (int nt = 0; nt < 8; nt++)
                #pragma unroll
                for (int i = 0; i < 4; i++) s[f][nt][i] = 0.0f;

        #pragma unroll
        for (int k8 = 0; k8 < 64; k8 += 8) {
            unsigned a[2][4];
            #pragma unroll
            for (int f = 0; f < 2; f++) {
                int r = rb + f * 16 + g;
                a[f][0] = Qt[(k8 + q) * QTS + r];
                a[f][1] = Qt[(k8 + q) * QTS + r + 8];
                a[f][2] = Qt[(k8 + 4 + q) * QTS + r];
                a[f][3] = Qt[(k8 + 4 + q) * QTS + r + 8];
            }
            #pragma unroll
            for (int nt = 0; nt < 8; nt++) {
                int c = nt * 8 + g;
                unsigned b0 = Kt[c * KTS + k8 + q];
                unsigned b1 = Kt[c * KTS + k8 + 4 + q];
                mma_tf32(s[0][nt][0], s[0][nt][1], s[0][nt][2], s[0][nt][3],
                         a[0][0], a[0][1], a[0][2], a[0][3], b0, b1);
                mma_tf32(s[1][nt][0], s[1][nt][1], s[1][nt][2], s[1][nt][3],
                         a[1][0], a[1][1], a[1][2], a[1][3], b0, b1);
            }
        }

        #pragma unroll
        for (int nt = 0; nt < 8; nt++) {
            float mk0 = maskF[nt * 8 + 2 * q];
            float mk1 = maskF[nt * 8 + 2 * q + 1];
            #pragma unroll
            for (int f = 0; f < 2; f++) {
                s[f][nt][0] = (mk0 == 0.0f) ? -10000.0f : s[f][nt][0];
                s[f][nt][2] = (mk0 == 0.0f) ? -10000.0f : s[f][nt][2];
                s[f][nt][1] = (mk1 == 0.0f) ? -10000.0f : s[f][nt][1];
                s[f][nt][3] = (mk1 == 0.0f) ? -10000.0f : s[f][nt][3];
            }
        }

        #pragma unroll
        for (int f = 0; f < 2; f++) {
            #pragma unroll
            for (int half = 0; half < 2; half++) {
                int ri = f * 2 + half;
                float mx = -1e30f;
                #pragma unroll
                for (int nt = 0; nt < 8; nt++) {
                    mx = fmaxf(mx, s[f][nt][half * 2 + 0]);
                    mx = fmaxf(mx, s[f][nt][half * 2 + 1]);
                }
                mx = fmaxf(mx, __shfl_xor_sync(0xffffffffu, mx, 1));
                mx = fmaxf(mx, __shfl_xor_sync(0xffffffffu, mx, 2));
                float mnew  = fmaxf(mrow[ri], mx);
                float alpha = __expf(mrow[ri] - mnew);
                float rs = 0.0f;
                #pragma unroll
                for (int nt = 0; nt < 8; nt++) {
                    float p0 = __expf(s[f][nt][half * 2 + 0] - mnew);
                    float p1 = __expf(s[f][nt][half * 2 + 1] - mnew);
                    s[f][nt][half * 2 + 0] = p0;
                    s[f][nt][half * 2 + 1] = p1;
                    rs += p0 + p1;
                }
                rs += __shfl_xor_sync(0xffffffffu, rs, 1);
                rs += __shfl_xor_sync(0xffffffffu, rs, 2);
                lrow[ri] = lrow[ri] * alpha + rs;
                mrow[ri] = mnew;
                #pragma unroll
                for (int nt = 0; nt < 8; nt++) {
                    o[f][nt][half * 2 + 0] *= alpha;
                    o[f][nt][half * 2 + 1] *= alpha;
                }
            }
        }

        #pragma unroll
        for (int f = 0; f < 2; f++) {
            int r = rb + f * 16 + g;
            #pragma unroll
            for (int nt = 0; nt < 8; nt++) {
                Ps[r * PTS + nt * 8 + 2 * q]           = f2tf(s[f][nt][0]);
                Ps[r * PTS + nt * 8 + 2 * q + 1]       = f2tf(s[f][nt][1]);
                Ps[(r + 8) * PTS + nt * 8 + 2 * q]     = f2tf(s[f][nt][2]);
                Ps[(r + 8) * PTS + nt * 8 + 2 * q + 1] = f2tf(s[f][nt][3]);
            }
        }
        __syncthreads();

        #pragma unroll
        for (int c8 = 0; c8 < 64; c8 += 8) {
            unsigned a[2][4];
            #pragma unroll
            for (int f = 0; f < 2; f++) {
                int r = rb + f * 16 + g;
                a[f][0] = Ps[r * PTS + c8 + q];
                a[f][1] = Ps[(r + 8) * PTS + c8 + q];
                a[f][2] = Ps[r * PTS + c8 + 4 + q];
                a[f][3] = Ps[(r + 8) * PTS + c8 + 4 + q];
            }
            #pragma unroll
            for (int nt = 0; nt < 8; nt++) {
                int d = nt * 8 + g;
                unsigned b0 = Vt[(c8 + q) * VTS + d];
                unsigned b1 = Vt[(c8 + 4 + q) * VTS + d];
                mma_tf32(o[0][nt][0], o[0][nt][1], o[0][nt][2], o[0][nt][3],
                         a[0][0], a[0][1], a[0][2], a[0][3], b0, b1);
                mma_tf32(o[1][nt][0], o[1][nt][1], o[1][nt][2], o[1][nt][3],
                         a[1][0], a[1][1], a[1][2], a[1][3], b0, b1);
            }
        }
    }

    #pragma unroll
    for (int f = 0; f < 2; f++) {
        float inv0 = 1.0f / lrow[f * 2 + 0];
        float inv1 = 1.0f / lrow[f * 2 + 1];
        #pragma unroll
        for (int nt = 0; nt < 8; nt++) {
            int d = nt * 8 + 2 * q;
            int rowA = q0 + rb + f * 16 + g;
            int rowB = rowA + 8;
            float2 v0 = make_float2(o[f][nt][0] * inv0, o[f][nt][1] * inv0);
            float2 v1 = make_float2(o[f][nt][2] * inv1, o[f][nt][3] * inv1);
            *(float2*)&g_x[((size_t)b * SS + rowA) * HID + h * DK + d] = v0;
            *(float2*)&g_x[((size_t)b * SS + rowB) * HID + h * DK + d] = v1;
        }
    }
}

// ---------------------------------------------------------------------------
extern "C" void kernel_launch(void* const* d_in, const int* in_sizes, int n_in,
                              void* d_out, int out_size)
{
    const float* query = (const float*)d_in[0];
    const float* key   = (const float*)d_in[1];
    const float* value = (const float*)d_in[2];
    const float* bias  = (const float*)d_in[3];
    const int*   mask  = (const int*)d_in[4];
    const float* wq = (const float*)d_in[5];
    const float* bq = (const float*)d_in[6];
    const float* wk = (const float*)d_in[7];
    const float* bk = (const float*)d_in[8];
    const float* wv = (const float*)d_in[9];
    const float* bv = (const float*)d_in[10];
    const float* wo = (const float*)d_in[11];
    const float* bo = (const float*)d_in[12];
    float* out = (float*)d_out;

    float *qp, *kp, *vp, *xp;
    cudaGetSymbolAddress((void**)&qp, g_q);
    cudaGetSymbolAddress((void**)&kp, g_k);
    cudaGetSymbolAddress((void**)&vp, g_v);
    cudaGetSymbolAddress((void**)&xp, g_x);

    cudaFuncSetAttribute(attn_tf32,
                         cudaFuncAttributeMaxDynamicSharedMemorySize, ATT_SMEM);

    QKVArgs args;
    args.q = query; args.k = key; args.v = value;
    args.wq = wq; args.wk = wk; args.wv = wv;
    args.bq = bq; args.bk = bk; args.bv = bv;
    args.bias = bias;
    args.oq = qp; args.ok = kp; args.ov = vp;

    qkv_gemm_tf32<<<dim3(HID / 128, MM / 128, 3), 256>>>(args);
    attn_tf32<<<dim3(SS / 128, BB * NH), 128, ATT_SMEM>>>(mask);
    out_gemm_tf32<<<dim3(HID / 128, MM / 128), 256>>>(xp, wo, bo, out);
}

// round 6
// speedup vs baseline: 1.8127x; 1.8127x over previous
#include <cuda_runtime.h>
#include <cuda_bf16.h>
#include <math.h>

#define BB 2
#define SS 2048
#define HID 1024
#define NH 16
#define DK 64
#define MM (BB*SS)   // 4096

// ---------------------------------------------------------------------------
// Scratch
// ---------------------------------------------------------------------------
__device__ float g_q[BB*NH*SS*DK];   // [b,h,s,d]
__device__ float g_k[BB*NH*SS*DK];
__device__ float g_v[BB*NH*SS*DK];
__device__ float g_x[BB*SS*HID];     // attention output [b,s,hid] (tf32-rounded)

// tf32-prerounded operands for cp.async GEMMs
__device__ float c_q[MM*HID];
__device__ float c_k[MM*HID];
__device__ float c_v[MM*HID];
__device__ float c_wq[HID*HID];
__device__ float c_wk[HID*HID];
__device__ float c_wv[HID*HID];
__device__ float c_wo[HID*HID];

// ---------------------------------------------------------------------------
// tf32 helpers
// ---------------------------------------------------------------------------
__device__ __forceinline__ unsigned f2tf(float x) {
    unsigned u;
    asm("cvt.rna.tf32.f32 %0, %1;" : "=r"(u) : "f"(x));
    return u;
}
__device__ __forceinline__ float f2tff(float x) {
    return __uint_as_float(f2tf(x));
}

__device__ __forceinline__ void mma_tf32(float& c0, float& c1, float& c2, float& c3,
                                         unsigned a0, unsigned a1, unsigned a2, unsigned a3,
                                         unsigned b0, unsigned b1) {
    asm volatile(
        "mma.sync.aligned.m16n8k8.row.col.f32.tf32.tf32.f32 "
        "{%0,%1,%2,%3},{%4,%5,%6,%7},{%8,%9},{%0,%1,%2,%3};"
        : "+f"(c0), "+f"(c1), "+f"(c2), "+f"(c3)
        : "r"(a0), "r"(a1), "r"(a2), "r"(a3), "r"(b0), "r"(b1));
}

__device__ __forceinline__ void cpasync16(const float* dst_smem, const float* src) {
    unsigned d = (unsigned)__cvta_generic_to_shared(dst_smem);
    asm volatile("cp.async.cg.shared.global [%0], [%1], 16;\n" :: "r"(d), "l"(src));
}
__device__ __forceinline__ void cp_commit() {
    asm volatile("cp.async.commit_group;\n");
}
template<int N>
__device__ __forceinline__ void cp_wait() {
    asm volatile("cp.async.wait_group %0;\n" :: "n"(N));
}

// ---------------------------------------------------------------------------
// Precompute: tf32-round weights; tf32-round inputs with (1+bias) scale on k,v
// ---------------------------------------------------------------------------
__global__ void __launch_bounds__(256)
prep_kernel(const float* __restrict__ query, const float* __restrict__ key,
            const float* __restrict__ value, const float* __restrict__ bias,
            const float* __restrict__ wq, const float* __restrict__ wk,
            const float* __restrict__ wv, const float* __restrict__ wo)
{
    const int y  = blockIdx.y;
    const int i4 = blockIdx.x * 256 + threadIdx.x;
    if (y < 3) {
        if (i4 < MM * HID / 4) {
            if (y == 0) {
                float4 v = ((const float4*)query)[i4];
                ((uint4*)c_q)[i4] = make_uint4(f2tf(v.x), f2tf(v.y), f2tf(v.z), f2tf(v.w));
            } else {
                int row = (i4 * 4) >> 10;
                float s = 1.0f + bias[row];
                const float* src = (y == 1) ? key : value;
                float* dst       = (y == 1) ? c_k : c_v;
                float4 v = ((const float4*)src)[i4];
                ((uint4*)dst)[i4] = make_uint4(f2tf(v.x * s), f2tf(v.y * s),
                                               f2tf(v.z * s), f2tf(v.w * s));
            }
        }
    } else {
        if (i4 < HID * HID / 4) {
            const float* src = (y == 3) ? wq : (y == 4) ? wk : (y == 5) ? wv : wo;
            float* dst       = (y == 3) ? c_wq : (y == 4) ? c_wk : (y == 5) ? c_wv : c_wo;
            float4 v = ((const float4*)src)[i4];
            ((uint4*)dst)[i4] = make_uint4(f2tf(v.x), f2tf(v.y), f2tf(v.z), f2tf(v.w));
        }
    }
}

// ---------------------------------------------------------------------------
// GEMM core: out = A[M,1024] @ W[1024,1024]^T + bias. A,W pre-rounded tf32.
// BM=128 BN=128 BK=16, 8 warps, warp tile 64x32. cp.async 3-stage pipeline,
// ONE __syncthreads per k-tile. Smem [row][20] (bank = 20g+q, conflict-free).
// ---------------------------------------------------------------------------
#define GST 20
#define NSTG 3
#define GEMM_SMEM (NSTG * 128 * GST * 2 * 4)

__device__ __forceinline__ void gemm_core(
    const float* __restrict__ A,
    const float* __restrict__ W,
    const float* __restrict__ bias,
    float* __restrict__ out,
    int transpose_out,
    float* sm, int bm0, int bn0)
{
    float (*sA)[128][GST] = (float (*)[128][GST])sm;
    float (*sB)[128][GST] = (float (*)[128][GST])(sm + NSTG * 128 * GST);

    const int tid   = threadIdx.x;
    const int warp  = tid >> 5;
    const int lane  = tid & 31;
    const int g     = lane >> 2;
    const int q     = lane & 3;
    const int warpM = warp >> 2;
    const int warpN = warp & 3;

    const int lrow  = tid >> 1;          // 0..127
    const int lhalf = (tid & 1) * 8;     // 0 or 8 (floats)

    const float* Ap = A + (size_t)(bm0 + lrow) * 1024 + lhalf;
    const float* Wp = W + (size_t)(bn0 + lrow) * 1024 + lhalf;

    // prologue: stages 0..NSTG-2
    #pragma unroll
    for (int s = 0; s < NSTG - 1; s++) {
        cpasync16(&sA[s][lrow][lhalf],     Ap + s * 16);
        cpasync16(&sA[s][lrow][lhalf + 4], Ap + s * 16 + 4);
        cpasync16(&sB[s][lrow][lhalf],     Wp + s * 16);
        cpasync16(&sB[s][lrow][lhalf + 4], Wp + s * 16 + 4);
        cp_commit();
    }

    float acc[4][4][4];
    #pragma unroll
    for (int mt = 0; mt < 4; mt++)
        #pragma unroll
        for (int nt = 0; nt < 4; nt++)
            #pragma unroll
            for (int i = 0; i < 4; i++) acc[mt][nt][i] = 0.0f;

    for (int kt = 0; kt < 64; kt++) {
        const int s = kt % NSTG;
        cp_wait<NSTG - 2>();
        __syncthreads();

        // issue stage kt+NSTG-1 (writes buffer consumed at kt-1; safe after sync)
        if (kt + NSTG - 1 < 64) {
            const int sn = (kt + NSTG - 1) % NSTG;
            const float* Ap2 = Ap + (kt + NSTG - 1) * 16;
            const float* Wp2 = Wp + (kt + NSTG - 1) * 16;
            cpasync16(&sA[sn][lrow][lhalf],     Ap2);
            cpasync16(&sA[sn][lrow][lhalf + 4], Ap2 + 4);
            cpasync16(&sB[sn][lrow][lhalf],     Wp2);
            cpasync16(&sB[sn][lrow][lhalf + 4], Wp2 + 4);
        }
        cp_commit();

        #pragma unroll
        for (int kk = 0; kk < 16; kk += 8) {
            unsigned af[4][4];
            #pragma unroll
            for (int mt = 0; mt < 4; mt++) {
                int r = warpM * 64 + mt * 16 + g;
                af[mt][0] = __float_as_uint(sA[s][r][kk + q]);
                af[mt][1] = __float_as_uint(sA[s][r + 8][kk + q]);
                af[mt][2] = __float_as_uint(sA[s][r][kk + 4 + q]);
                af[mt][3] = __float_as_uint(sA[s][r + 8][kk + 4 + q]);
            }
            unsigned bf[4][2];
            #pragma unroll
            for (int nt = 0; nt < 4; nt++) {
                int n = warpN * 32 + nt * 8 + g;
                bf[nt][0] = __float_as_uint(sB[s][n][kk + q]);
                bf[nt][1] = __float_as_uint(sB[s][n][kk + 4 + q]);
            }
            #pragma unroll
            for (int mt = 0; mt < 4; mt++)
                #pragma unroll
                for (int nt = 0; nt < 4; nt++)
                    mma_tf32(acc[mt][nt][0], acc[mt][nt][1], acc[mt][nt][2], acc[mt][nt][3],
                             af[mt][0], af[mt][1], af[mt][2], af[mt][3],
                             bf[nt][0], bf[nt][1]);
        }
    }

    #pragma unroll
    for (int mt = 0; mt < 4; mt++) {
        #pragma unroll
        for (int nt = 0; nt < 4; nt++) {
            int col = bn0 + warpN * 32 + nt * 8 + 2 * q;
            float b0 = bias[col], b1 = bias[col + 1];
            #pragma unroll
            for (int half = 0; half < 2; half++) {
                int row = bm0 + warpM * 64 + mt * 16 + g + half * 8;
                float2 v;
                v.x = acc[mt][nt][half * 2 + 0] + b0;
                v.y = acc[mt][nt][half * 2 + 1] + b1;
                if (transpose_out) {
                    int bb = row >> 11, ss = row & 2047;
                    int hh = col >> 6, dd = col & 63;
                    *(float2*)&out[(((size_t)bb * NH + hh) * SS + ss) * DK + dd] = v;
                } else {
                    *(float2*)&out[(size_t)row * HID + col] = v;
                }
            }
        }
    }
}

__global__ void __launch_bounds__(256)
qkv_gemm(const float* __restrict__ bq,
         const float* __restrict__ bk,
         const float* __restrict__ bv)
{
    extern __shared__ float sm[];
    const int z = blockIdx.z;
    const float* A  = (z == 0) ? c_q  : (z == 1) ? c_k  : c_v;
    const float* W  = (z == 0) ? c_wq : (z == 1) ? c_wk : c_wv;
    const float* bb = (z == 0) ? bq   : (z == 1) ? bk   : bv;
    float* out      = (z == 0) ? g_q  : (z == 1) ? g_k  : g_v;
    gemm_core(A, W, bb, out, 1, sm, blockIdx.y * 128, blockIdx.x * 128);
}

__global__ void __launch_bounds__(256)
out_gemm(const float* __restrict__ bo, float* __restrict__ out)
{
    extern __shared__ float sm[];
    gemm_core(g_x, c_wo, bo, out, 0, sm, blockIdx.y * 128, blockIdx.x * 128);
}

// ---------------------------------------------------------------------------
// Flash attention, tf32 mma, 4 warps, warp tile m32 x n64 (R4 version;
// epilogue writes tf32-rounded values so out_gemm can stage raw bytes).
// ---------------------------------------------------------------------------
#define QTS 136
#define KTS 68
#define VTS 72
#define PTS 68
#define ATT_SMEM ((64*QTS + 64*KTS + 64*VTS + 128*PTS + 64) * 4)

__global__ void __launch_bounds__(128)
attn_tf32(const int* __restrict__ mask)
{
    extern __shared__ unsigned smu[];
    unsigned* Qt = smu;                      // [64][136]
    unsigned* Kt = Qt + 64 * QTS;            // [64][68]
    unsigned* Vt = Kt + 64 * KTS;            // [64][72]
    unsigned* Ps = Vt + 64 * VTS;            // [128][68]
    float* maskF = (float*)(Ps + 128 * PTS); // [64]

    const int tid  = threadIdx.x;
    const int warp = tid >> 5;
    const int lane = tid & 31;
    const int g    = lane >> 2;
    const int q    = lane & 3;
    const int rb   = warp * 32;

    const int bh = blockIdx.y;
    const int b  = bh >> 4;
    const int h  = bh & 15;
    const int q0 = blockIdx.x * 128;

    const float* qptr = g_q + ((size_t)bh * SS + q0) * DK;
    for (int e = tid; e < 128 * 16; e += 128) {
        int r  = e >> 4;
        int d4 = (e & 15) << 2;
        float4 v = *(const float4*)(qptr + (size_t)r * DK + d4);
        Qt[(d4 + 0) * QTS + r] = f2tf(v.x * 0.125f);
        Qt[(d4 + 1) * QTS + r] = f2tf(v.y * 0.125f);
        Qt[(d4 + 2) * QTS + r] = f2tf(v.z * 0.125f);
        Qt[(d4 + 3) * QTS + r] = f2tf(v.w * 0.125f);
    }

    float o[2][8][4];
    #pragma unroll
    for (int f = 0; f < 2; f++)
        #pragma unroll
        for (int nt = 0; nt < 8; nt++)
            #pragma unroll
            for (int i = 0; i < 4; i++) o[f][nt][i] = 0.0f;
    float mrow[4] = {-1e30f, -1e30f, -1e30f, -1e30f};
    float lrow[4] = {0.0f, 0.0f, 0.0f, 0.0f};

    for (int kt = 0; kt < SS / 64; kt++) {
        __syncthreads();

        const float* kp = g_k + ((size_t)bh * SS + kt * 64) * DK;
        const float* vp = g_v + ((size_t)bh * SS + kt * 64) * DK;
        for (int e = tid; e < 64 * 16; e += 128) {
            int c  = e >> 4;
            int d4 = (e & 15) << 2;
            float4 kv = *(const float4*)(kp + (size_t)c * DK + d4);
            uint4 ku = make_uint4(f2tf(kv.x), f2tf(kv.y), f2tf(kv.z), f2tf(kv.w));
            *(uint4*)&Kt[c * KTS + d4] = ku;
            float4 vv = *(const float4*)(vp + (size_t)c * DK + d4);
            uint4 vu = make_uint4(f2tf(vv.x), f2tf(vv.y), f2tf(vv.z), f2tf(vv.w));
            *(uint4*)&Vt[c * VTS + d4] = vu;
        }
        if (tid < 64)
            maskF[tid] = (mask[b * SS + kt * 64 + tid] == 0) ? 0.0f : 1.0f;
        __syncthreads();

        float s[2][8][4];
        #pragma unroll
        for (int f = 0; f < 2; f++)
            #pragma unroll
            for (int nt = 0; nt < 8; nt++)
                #pragma unroll
                for (int i = 0; i < 4; i++) s[f][nt][i] = 0.0f;

        #pragma unroll
        for (int k8 = 0; k8 < 64; k8 += 8) {
            unsigned a[2][4];
            #pragma unroll
            for (int f = 0; f < 2; f++) {
                int r = rb + f * 16 + g;
                a[f][0] = Qt[(k8 + q) * QTS + r];
                a[f][1] = Qt[(k8 + q) * QTS + r + 8];
                a[f][2] = Qt[(k8 + 4 + q) * QTS + r];
                a[f][3] = Qt[(k8 + 4 + q) * QTS + r + 8];
            }
            #pragma unroll
            for (int nt = 0; nt < 8; nt++) {
                int c = nt * 8 + g;
                unsigned b0 = Kt[c * KTS + k8 + q];
                unsigned b1 = Kt[c * KTS + k8 + 4 + q];
                mma_tf32(s[0][nt][0], s[0][nt][1], s[0][nt][2], s[0][nt][3],
                         a[0][0], a[0][1], a[0][2], a[0][3], b0, b1);
                mma_tf32(s[1][nt][0], s[1][nt][1], s[1][nt][2], s[1][nt][3],
                         a[1][0], a[1][1], a[1][2], a[1][3], b0, b1);
            }
        }

        #pragma unroll
        for (int nt = 0; nt < 8; nt++) {
            float mk0 = maskF[nt * 8 + 2 * q];
            float mk1 = maskF[nt * 8 + 2 * q + 1];
            #pragma unroll
            for (int f = 0; f < 2; f++) {
                s[f][nt][0] = (mk0 == 0.0f) ? -10000.0f : s[f][nt][0];
                s[f][nt][2] = (mk0 == 0.0f) ? -10000.0f : s[f][nt][2];
                s[f][nt][1] = (mk1 == 0.0f) ? -10000.0f : s[f][nt][1];
                s[f][nt][3] = (mk1 == 0.0f) ? -10000.0f : s[f][nt][3];
            }
        }

        #pragma unroll
        for (int f = 0; f < 2; f++) {
            #pragma unroll
            for (int half = 0; half < 2; half++) {
                int ri = f * 2 + half;
                float mx = -1e30f;
                #pragma unroll
                for (int nt = 0; nt < 8; nt++) {
                    mx = fmaxf(mx, s[f][nt][half * 2 + 0]);
                    mx = fmaxf(mx, s[f][nt][half * 2 + 1]);
                }
                mx = fmaxf(mx, __shfl_xor_sync(0xffffffffu, mx, 1));
                mx = fmaxf(mx, __shfl_xor_sync(0xffffffffu, mx, 2));
                float mnew  = fmaxf(mrow[ri], mx);
                float alpha = __expf(mrow[ri] - mnew);
                float rs = 0.0f;
                #pragma unroll
                for (int nt = 0; nt < 8; nt++) {
                    float p0 = __expf(s[f][nt][half * 2 + 0] - mnew);
                    float p1 = __expf(s[f][nt][half * 2 + 1] - mnew);
                    s[f][nt][half * 2 + 0] = p0;
                    s[f][nt][half * 2 + 1] = p1;
                    rs += p0 + p1;
                }
                rs += __shfl_xor_sync(0xffffffffu, rs, 1);
                rs += __shfl_xor_sync(0xffffffffu, rs, 2);
                lrow[ri] = lrow[ri] * alpha + rs;
                mrow[ri] = mnew;
                #pragma unroll
                for (int nt = 0; nt < 8; nt++) {
                    o[f][nt][half * 2 + 0] *= alpha;
                    o[f][nt][half * 2 + 1] *= alpha;
                }
            }
        }

        #pragma unroll
        for (int f = 0; f < 2; f++) {
            int r = rb + f * 16 + g;
            #pragma unroll
            for (int nt = 0; nt < 8; nt++) {
                Ps[r * PTS + nt * 8 + 2 * q]           = f2tf(s[f][nt][0]);
                Ps[r * PTS + nt * 8 + 2 * q + 1]       = f2tf(s[f][nt][1]);
                Ps[(r + 8) * PTS + nt * 8 + 2 * q]     = f2tf(s[f][nt][2]);
                Ps[(r + 8) * PTS + nt * 8 + 2 * q + 1] = f2tf(s[f][nt][3]);
            }
        }
        __syncthreads();

        #pragma unroll
        for (int c8 = 0; c8 < 64; c8 += 8) {
            unsigned a[2][4];
            #pragma unroll
            for (int f = 0; f < 2; f++) {
                int r = rb + f * 16 + g;
                a[f][0] = Ps[r * PTS + c8 + q];
                a[f][1] = Ps[(r + 8) * PTS + c8 + q];
                a[f][2] = Ps[r * PTS + c8 + 4 + q];
                a[f][3] = Ps[(r + 8) * PTS + c8 + 4 + q];
            }
            #pragma unroll
            for (int nt = 0; nt < 8; nt++) {
                int d = nt * 8 + g;
                unsigned b0 = Vt[(c8 + q) * VTS + d];
                unsigned b1 = Vt[(c8 + 4 + q) * VTS + d];
                mma_tf32(o[0][nt][0], o[0][nt][1], o[0][nt][2], o[0][nt][3],
                         a[0][0], a[0][1], a[0][2], a[0][3], b0, b1);
                mma_tf32(o[1][nt][0], o[1][nt][1], o[1][nt][2], o[1][nt][3],
                         a[1][0], a[1][1], a[1][2], a[1][3], b0, b1);
            }
        }
    }

    // Epilogue: normalize, tf32-round, write [b,s,hid]
    #pragma unroll
    for (int f = 0; f < 2; f++) {
        float inv0 = 1.0f / lrow[f * 2 + 0];
        float inv1 = 1.0f / lrow[f * 2 + 1];
        #pragma unroll
        for (int nt = 0; nt < 8; nt++) {
            int d = nt * 8 + 2 * q;
            int rowA = q0 + rb + f * 16 + g;
            int rowB = rowA + 8;
            float2 v0 = make_float2(f2tff(o[f][nt][0] * inv0), f2tff(o[f][nt][1] * inv0));
            float2 v1 = make_float2(f2tff(o[f][nt][2] * inv1), f2tff(o[f][nt][3] * inv1));
            *(float2*)&g_x[((size_t)b * SS + rowA) * HID + h * DK + d] = v0;
            *(float2*)&g_x[((size_t)b * SS + rowB) * HID + h * DK + d] = v1;
        }
    }
}

// ---------------------------------------------------------------------------
extern "C" void kernel_launch(void* const* d_in, const int* in_sizes, int n_in,
                              void* d_out, int out_size)
{
    const float* query = (const float*)d_in[0];
    const float* key   = (const float*)d_in[1];
    const float* value = (const float*)d_in[2];
    const float* bias  = (const float*)d_in[3];
    const int*   mask  = (const int*)d_in[4];
    const float* wq = (const float*)d_in[5];
    const float* bq = (const float*)d_in[6];
    const float* wk = (const float*)d_in[7];
    const float* bk = (const float*)d_in[8];
    const float* wv = (const float*)d_in[9];
    const float* bv = (const float*)d_in[10];
    const float* wo = (const float*)d_in[11];
    const float* bo = (const float*)d_in[12];
    float* out = (float*)d_out;

    cudaFuncSetAttribute(attn_tf32,
                         cudaFuncAttributeMaxDynamicSharedMemorySize, ATT_SMEM);
    cudaFuncSetAttribute(qkv_gemm,
                         cudaFuncAttributeMaxDynamicSharedMemorySize, GEMM_SMEM);
    cudaFuncSetAttribute(out_gemm,
                         cudaFuncAttributeMaxDynamicSharedMemorySize, GEMM_SMEM);

    prep_kernel<<<dim3(4096, 7), 256>>>(query, key, value, bias, wq, wk, wv, wo);
    qkv_gemm<<<dim3(HID / 128, MM / 128, 3), 256, GEMM_SMEM>>>(bq, bk, bv);
    attn_tf32<<<dim3(SS / 128, BB * NH), 128, ATT_SMEM>>>(mask);
    out_gemm<<<dim3(HID / 128, MM / 128), 256, GEMM_SMEM>>>(bo, out);
}

// round 11
// speedup vs baseline: 1.9892x; 1.0974x over previous
#include <cuda_runtime.h>
#include <cuda_bf16.h>
#include <math.h>

#define BB 2
#define SS 2048
#define HID 1024
#define NH 16
#define DK 64
#define MM (BB*SS)   // 4096

// ---------------------------------------------------------------------------
// Scratch
// ---------------------------------------------------------------------------
__device__ float g_q[BB*NH*SS*DK];   // [b,h,s,d]
__device__ float g_k[BB*NH*SS*DK];
__device__ float g_v[BB*NH*SS*DK];
__device__ float g_x[BB*SS*HID];     // attn out [b,s,hid], tf32, k-PERMUTED

// tf32-prerounded + k-permuted operands for cp.async GEMMs
__device__ float c_q[MM*HID];
__device__ float c_k[MM*HID];
__device__ float c_v[MM*HID];
__device__ float c_wq[HID*HID];
__device__ float c_wk[HID*HID];
__device__ float c_wv[HID*HID];
__device__ float c_wo[HID*HID];

// ---------------------------------------------------------------------------
// tf32 helpers
// ---------------------------------------------------------------------------
__device__ __forceinline__ unsigned f2tf(float x) {
    unsigned u;
    asm("cvt.rna.tf32.f32 %0, %1;" : "=r"(u) : "f"(x));
    return u;
}
__device__ __forceinline__ float f2tff(float x) {
    return __uint_as_float(f2tf(x));
}

__device__ __forceinline__ void mma_tf32(float& c0, float& c1, float& c2, float& c3,
                                         unsigned a0, unsigned a1, unsigned a2, unsigned a3,
                                         unsigned b0, unsigned b1) {
    asm volatile(
        "mma.sync.aligned.m16n8k8.row.col.f32.tf32.tf32.f32 "
        "{%0,%1,%2,%3},{%4,%5,%6,%7},{%8,%9},{%0,%1,%2,%3};"
        : "+f"(c0), "+f"(c1), "+f"(c2), "+f"(c3)
        : "r"(a0), "r"(a1), "r"(a2), "r"(a3), "r"(b0), "r"(b1));
}

__device__ __forceinline__ void cpasync16(const float* dst_smem, const float* src) {
    unsigned d = (unsigned)__cvta_generic_to_shared(dst_smem);
    asm volatile("cp.async.cg.shared.global [%0], [%1], 16;\n" :: "r"(d), "l"(src));
}
__device__ __forceinline__ void cp_commit() {
    asm volatile("cp.async.commit_group;\n");
}
template<int N>
__device__ __forceinline__ void cp_wait() {
    asm volatile("cp.async.wait_group %0;\n" :: "n"(N));
}

// ---------------------------------------------------------------------------
// Precompute: tf32-round + k-permute (within-16: p=(k%4)*4+k/4, involution).
// Inputs k,v also scaled by (1+bias[row]).
// ---------------------------------------------------------------------------
__global__ void __launch_bounds__(256)
prep_kernel(const float* __restrict__ query, const float* __restrict__ key,
            const float* __restrict__ value, const float* __restrict__ bias,
            const float* __restrict__ wq, const float* __restrict__ wk,
            const float* __restrict__ wv, const float* __restrict__ wo)
{
    const int y  = blockIdx.y;
    const int i4 = blockIdx.x * 256 + threadIdx.x;
    const int nEl = (y < 3) ? (MM * HID / 4) : (HID * HID / 4);
    if (i4 >= nEl) return;

    const float* src;
    float* dst;
    float s = 1.0f;
    if (y == 0)      { src = query; dst = c_q; }
    else if (y == 1) { src = key;   dst = c_k; s = 1.0f + bias[(i4 * 4) >> 10]; }
    else if (y == 2) { src = value; dst = c_v; s = 1.0f + bias[(i4 * 4) >> 10]; }
    else if (y == 3) { src = wq; dst = c_wq; }
    else if (y == 4) { src = wk; dst = c_wk; }
    else if (y == 5) { src = wv; dst = c_wv; }
    else             { src = wo; dst = c_wo; }

    float4 v = ((const float4*)src)[i4];
    int flat = i4 * 4;
    int blk  = flat & ~15;              // 16-aligned block base
    int a    = (flat >> 2) & 3;         // which 4-group within block
    dst[blk + 0 * 4 + a] = f2tff(v.x * s);
    dst[blk + 1 * 4 + a] = f2tff(v.y * s);
    dst[blk + 2 * 4 + a] = f2tff(v.z * s);
    dst[blk + 3 * 4 + a] = f2tff(v.w * s);
}

// ---------------------------------------------------------------------------
// GEMM core: out = A[M,1024] @ W[1024,1024]^T + bias. A,W tf32 + k-permuted.
// BM=128 BN=128 BK=16, 8 warps, warp tile 64x32. cp.async 4-stage pipeline.
// Smem [row][16] stride 16: LDS.128 frag loads, conflict-free per phase.
// Per 16-k tile per warp: 12 LDS.128 + 32 MMA.
// ---------------------------------------------------------------------------
#define GST 16
#define NSTG 4
#define GEMM_SMEM (NSTG * 128 * GST * 2 * 4)   // 64 KB

__device__ __forceinline__ void gemm_core(
    const float* __restrict__ A,
    const float* __restrict__ W,
    const float* __restrict__ bias,
    float* __restrict__ out,
    int transpose_out,
    float* sm, int bm0, int bn0)
{
    float (*sA)[128][GST] = (float (*)[128][GST])sm;
    float (*sB)[128][GST] = (float (*)[128][GST])(sm + NSTG * 128 * GST);

    const int tid   = threadIdx.x;
    const int warp  = tid >> 5;
    const int lane  = tid & 31;
    const int g     = lane >> 2;
    const int q     = lane & 3;
    const int warpM = warp >> 2;
    const int warpN = warp & 3;

    const int lrow  = tid >> 1;          // 0..127
    const int lhalf = (tid & 1) * 8;     // 0 or 8 floats

    const float* Ap = A + (size_t)(bm0 + lrow) * 1024 + lhalf;
    const float* Wp = W + (size_t)(bn0 + lrow) * 1024 + lhalf;

    #pragma unroll
    for (int s = 0; s < NSTG - 1; s++) {
        cpasync16(&sA[s][lrow][lhalf],     Ap + s * 16);
        cpasync16(&sA[s][lrow][lhalf + 4], Ap + s * 16 + 4);
        cpasync16(&sB[s][lrow][lhalf],     Wp + s * 16);
        cpasync16(&sB[s][lrow][lhalf + 4], Wp + s * 16 + 4);
        cp_commit();
    }

    float acc[4][4][4];
    #pragma unroll
    for (int mt = 0; mt < 4; mt++)
        #pragma unroll
        for (int nt = 0; nt < 4; nt++)
            #pragma unroll
            for (int i = 0; i < 4; i++) acc[mt][nt][i] = 0.0f;

    for (int kt = 0; kt < 64; kt++) {
        const int s = kt % NSTG;
        cp_wait<NSTG - 2>();
        __syncthreads();

        if (kt + NSTG - 1 < 64) {
            const int sn = (kt + NSTG - 1) % NSTG;
            const float* Ap2 = Ap + (kt + NSTG - 1) * 16;
            const float* Wp2 = Wp + (kt + NSTG - 1) * 16;
            cpasync16(&sA[sn][lrow][lhalf],     Ap2);
            cpasync16(&sA[sn][lrow][lhalf + 4], Ap2 + 4);
            cpasync16(&sB[sn][lrow][lhalf],     Wp2);
            cpasync16(&sB[sn][lrow][lhalf + 4], Wp2 + 4);
        }
        cp_commit();

        // B fragments: one LDS.128 per nt covers both k-halves
        float4 Bf[4];
        #pragma unroll
        for (int nt = 0; nt < 4; nt++)
            Bf[nt] = *(const float4*)&sB[s][warpN * 32 + nt * 8 + g][4 * q];

        #pragma unroll
        for (int mt = 0; mt < 4; mt++) {
            int r = warpM * 64 + mt * 16 + g;
            float4 lo = *(const float4*)&sA[s][r][4 * q];
            float4 hi = *(const float4*)&sA[s][r + 8][4 * q];
            #pragma unroll
            for (int nt = 0; nt < 4; nt++) {
                mma_tf32(acc[mt][nt][0], acc[mt][nt][1], acc[mt][nt][2], acc[mt][nt][3],
                         __float_as_uint(lo.x), __float_as_uint(hi.x),
                         __float_as_uint(lo.y), __float_as_uint(hi.y),
                         __float_as_uint(Bf[nt].x), __float_as_uint(Bf[nt].y));
                mma_tf32(acc[mt][nt][0], acc[mt][nt][1], acc[mt][nt][2], acc[mt][nt][3],
                         __float_as_uint(lo.z), __float_as_uint(hi.z),
                         __float_as_uint(lo.w), __float_as_uint(hi.w),
                         __float_as_uint(Bf[nt].z), __float_as_uint(Bf[nt].w));
            }
        }
    }

    #pragma unroll
    for (int mt = 0; mt < 4; mt++) {
        #pragma unroll
        for (int nt = 0; nt < 4; nt++) {
            int col = bn0 + warpN * 32 + nt * 8 + 2 * q;
            float b0 = bias[col], b1 = bias[col + 1];
            #pragma unroll
            for (int half = 0; half < 2; half++) {
                int row = bm0 + warpM * 64 + mt * 16 + g + half * 8;
                float2 v;
                v.x = acc[mt][nt][half * 2 + 0] + b0;
                v.y = acc[mt][nt][half * 2 + 1] + b1;
                if (transpose_out) {
                    int bb = row >> 11, ss = row & 2047;
                    int hh = col >> 6, dd = col & 63;
                    *(float2*)&out[(((size_t)bb * NH + hh) * SS + ss) * DK + dd] = v;
                } else {
                    *(float2*)&out[(size_t)row * HID + col] = v;
                }
            }
        }
    }
}

__global__ void __launch_bounds__(256)
qkv_gemm(const float* __restrict__ bq,
         const float* __restrict__ bk,
         const float* __restrict__ bv)
{
    extern __shared__ float sm[];
    const int z = blockIdx.z;
    const float* A  = (z == 0) ? c_q  : (z == 1) ? c_k  : c_v;
    const float* W  = (z == 0) ? c_wq : (z == 1) ? c_wk : c_wv;
    const float* bb = (z == 0) ? bq   : (z == 1) ? bk   : bv;
    float* out      = (z == 0) ? g_q  : (z == 1) ? g_k  : g_v;
    gemm_core(A, W, bb, out, 1, sm, blockIdx.y * 128, blockIdx.x * 128);
}

__global__ void __launch_bounds__(256)
out_gemm(const float* __restrict__ bo, float* __restrict__ out)
{
    extern __shared__ float sm[];
    gemm_core(g_x, c_wo, bo, out, 0, sm, blockIdx.y * 128, blockIdx.x * 128);
}

// ---------------------------------------------------------------------------
// Flash attention, tf32 mma, 4 warps, warp tile m32 x n64.
// Epilogue writes g_x tf32-rounded AND k-permuted for out_gemm staging.
// ---------------------------------------------------------------------------
#define QTS 136
#define KTS 68
#define VTS 72
#define PTS 68
#define ATT_SMEM ((64*QTS + 64*KTS + 64*VTS + 128*PTS + 64) * 4)

__global__ void __launch_bounds__(128)
attn_tf32(const int* __restrict__ mask)
{
    extern __shared__ unsigned smu[];
    unsigned* Qt = smu;                      // [64][136]
    unsigned* Kt = Qt + 64 * QTS;            // [64][68]
    unsigned* Vt = Kt + 64 * KTS;            // [64][72]
    unsigned* Ps = Vt + 64 * VTS;            // [128][68]
    float* maskF = (float*)(Ps + 128 * PTS); // [64]

    const int tid  = threadIdx.x;
    const int warp = tid >> 5;
    const int lane = tid & 31;
    const int g    = lane >> 2;
    const int q    = lane & 3;
    const int rb   = warp * 32;

    const int bh = blockIdx.y;
    const int b  = bh >> 4;
    const int h  = bh & 15;
    const int q0 = blockIdx.x * 128;

    const float* qptr = g_q + ((size_t)bh * SS + q0) * DK;
    for (int e = tid; e < 128 * 16; e += 128) {
        int r  = e >> 4;
        int d4 = (e & 15) << 2;
        float4 v = *(const float4*)(qptr + (size_t)r * DK + d4);
        Qt[(d4 + 0) * QTS + r] = f2tf(v.x * 0.125f);
        Qt[(d4 + 1) * QTS + r] = f2tf(v.y * 0.125f);
        Qt[(d4 + 2) * QTS + r] = f2tf(v.z * 0.125f);
        Qt[(d4 + 3) * QTS + r] = f2tf(v.w * 0.125f);
    }

    float o[2][8][4];
    #pragma unroll
    for (int f = 0; f < 2; f++)
        #pragma unroll
        for (int nt = 0; nt < 8; nt++)
            #pragma unroll
            for (int i = 0; i < 4; i++) o[f][nt][i] = 0.0f;
    float mrow[4] = {-1e30f, -1e30f, -1e30f, -1e30f};
    float lrow[4] = {0.0f, 0.0f, 0.0f, 0.0f};

    for (int kt = 0; kt < SS / 64; kt++) {
        __syncthreads();

        const float* kp = g_k + ((size_t)bh * SS + kt * 64) * DK;
        const float* vp = g_v + ((size_t)bh * SS + kt * 64) * DK;
        for (int e = tid; e < 64 * 16; e += 128) {
            int c  = e >> 4;
            int d4 = (e & 15) << 2;
            float4 kv = *(const float4*)(kp + (size_t)c * DK + d4);
            uint4 ku = make_uint4(f2tf(kv.x), f2tf(kv.y), f2tf(kv.z), f2tf(kv.w));
            *(uint4*)&Kt[c * KTS + d4] = ku;
            float4 vv = *(const float4*)(vp + (size_t)c * DK + d4);
            uint4 vu = make_uint4(f2tf(vv.x), f2tf(vv.y), f2tf(vv.z), f2tf(vv.w));
            *(uint4*)&Vt[c * VTS + d4] = vu;
        }
        if (tid < 64)
            maskF[tid] = (mask[b * SS + kt * 64 + tid] == 0) ? 0.0f : 1.0f;
        __syncthreads();

        float s[2][8][4];
        #pragma unroll
        for (int f = 0; f < 2; f++)
            #pragma unroll
            for (int nt = 0; nt < 8; nt++)
                #pragma unroll
                for (int i = 0; i < 4; i++) s[f][nt][i] = 0.0f;

        #pragma unroll
        for (int k8 = 0; k8 < 64; k8 += 8) {
            unsigned a[2][4];
            #pragma unroll
            for (int f = 0; f < 2; f++) {
                int r = rb + f * 16 + g;
                a[f][0] = Qt[(k8 + q) * QTS + r];
                a[f][1] = Qt[(k8 + q) * QTS + r + 8];
                a[f][2] = Qt[(k8 + 4 + q) * QTS + r];
                a[f][3] = Qt[(k8 + 4 + q) * QTS + r + 8];
            }
            #pragma unroll
            for (int nt = 0; nt < 8; nt++) {
                int c = nt * 8 + g;
                unsigned b0 = Kt[c * KTS + k8 + q];
                unsigned b1 = Kt[c * KTS + k8 + 4 + q];
                mma_tf32(s[0][nt][0], s[0][nt][1], s[0][nt][2], s[0][nt][3],
                         a[0][0], a[0][1], a[0][2], a[0][3], b0, b1);
                mma_tf32(s[1][nt][0], s[1][nt][1], s[1][nt][2], s[1][nt][3],
                         a[1][0], a[1][1], a[1][2], a[1][3], b0, b1);
            }
        }

        #pragma unroll
        for (int nt = 0; nt < 8; nt++) {
            float mk0 = maskF[nt * 8 + 2 * q];
            float mk1 = maskF[nt * 8 + 2 * q + 1];
            #pragma unroll
            for (int f = 0; f < 2; f++) {
                s[f][nt][0] = (mk0 == 0.0f) ? -10000.0f : s[f][nt][0];
                s[f][nt][2] = (mk0 == 0.0f) ? -10000.0f : s[f][nt][2];
                s[f][nt][1] = (mk1 == 0.0f) ? -10000.0f : s[f][nt][1];
                s[f][nt][3] = (mk1 == 0.0f) ? -10000.0f : s[f][nt][3];
            }
        }

        #pragma unroll
        for (int f = 0; f < 2; f++) {
            #pragma unroll
            for (int half = 0; half < 2; half++) {
                int ri = f * 2 + half;
                float mx = -1e30f;
                #pragma unroll
                for (int nt = 0; nt < 8; nt++) {
                    mx = fmaxf(mx, s[f][nt][half * 2 + 0]);
                    mx = fmaxf(mx, s[f][nt][half * 2 + 1]);
                }
                mx = fmaxf(mx, __shfl_xor_sync(0xffffffffu, mx, 1));
                mx = fmaxf(mx, __shfl_xor_sync(0xffffffffu, mx, 2));
                float mnew  = fmaxf(mrow[ri], mx);
                float alpha = __expf(mrow[ri] - mnew);
                float rs = 0.0f;
                #pragma unroll
                for (int nt = 0; nt < 8; nt++) {
                    float p0 = __expf(s[f][nt][half * 2 + 0] - mnew);
                    float p1 = __expf(s[f][nt][half * 2 + 1] - mnew);
                    s[f][nt][half * 2 + 0] = p0;
                    s[f][nt][half * 2 + 1] = p1;
                    rs += p0 + p1;
                }
                rs += __shfl_xor_sync(0xffffffffu, rs, 1);
                rs += __shfl_xor_sync(0xffffffffu, rs, 2);
                lrow[ri] = lrow[ri] * alpha + rs;
                mrow[ri] = mnew;
                #pragma unroll
                for (int nt = 0; nt < 8; nt++) {
                    o[f][nt][half * 2 + 0] *= alpha;
                    o[f][nt][half * 2 + 1] *= alpha;
                }
            }
        }

        #pragma unroll
        for (int f = 0; f < 2; f++) {
            int r = rb + f * 16 + g;
            #pragma unroll
            for (int nt = 0; nt < 8; nt++) {
                Ps[r * PTS + nt * 8 + 2 * q]           = f2tf(s[f][nt][0]);
                Ps[r * PTS + nt * 8 + 2 * q + 1]       = f2tf(s[f][nt][1]);
                Ps[(r + 8) * PTS + nt * 8 + 2 * q]     = f2tf(s[f][nt][2]);
                Ps[(r + 8) * PTS + nt * 8 + 2 * q + 1] = f2tf(s[f][nt][3]);
            }
        }
        __syncthreads();

        #pragma unroll
        for (int c8 = 0; c8 < 64; c8 += 8) {
            unsigned a[2][4];
            #pragma unroll
            for (int f = 0; f < 2; f++) {
                int r = rb + f * 16 + g;
                a[f][0] = Ps[r * PTS + c8 + q];
                a[f][1] = Ps[(r + 8) * PTS + c8 + q];
                a[f][2] = Ps[r * PTS + c8 + 4 + q];
                a[f][3] = Ps[(r + 8) * PTS + c8 + 4 + q];
            }
            #pragma unroll
            for (int nt = 0; nt < 8; nt++) {
                int d = nt * 8 + g;
                unsigned b0 = Vt[(c8 + q) * VTS + d];
                unsigned b1 = Vt[(c8 + 4 + q) * VTS + d];
                mma_tf32(o[0][nt][0], o[0][nt][1], o[0][nt][2], o[0][nt][3],
                         a[0][0], a[0][1], a[0][2], a[0][3], b0, b1);
                mma_tf32(o[1][nt][0], o[1][nt][1], o[1][nt][2], o[1][nt][3],
                         a[1][0], a[1][1], a[1][2], a[1][3], b0, b1);
            }
        }
    }

    // Epilogue: normalize, tf32-round, write g_x with k-permuted columns
    #pragma unroll
    for (int f = 0; f < 2; f++) {
        float inv0 = 1.0f / lrow[f * 2 + 0];
        float inv1 = 1.0f / lrow[f * 2 + 1];
        #pragma unroll
        for (int nt = 0; nt < 8; nt++) {
            int w0  = nt * 8 + 2 * q;           // 0..62, even
            int blk = w0 & ~15;
            int wa  = w0 & 15;
            int wb  = wa + 1;
            int pa  = ((wa & 3) << 2) | (wa >> 2);
            int pb  = ((wb & 3) << 2) | (wb >> 2);
            int base = h * DK + blk;
            int rowA = q0 + rb + f * 16 + g;
            int rowB = rowA + 8;
            size_t offA = ((size_t)b * SS + rowA) * HID + base;
            size_t offB = ((size_t)b * SS + rowB) * HID + base;
            g_x[offA + pa] = f2tff(o[f][nt][0] * inv0);
            g_x[offA + pb] = f2tff(o[f][nt][1] * inv0);
            g_x[offB + pa] = f2tff(o[f][nt][2] * inv1);
            g_x[offB + pb] = f2tff(o[f][nt][3] * inv1);
        }
    }
}

// ---------------------------------------------------------------------------
extern "C" void kernel_launch(void* const* d_in, const int* in_sizes, int n_in,
                              void* d_out, int out_size)
{
    const float* query = (const float*)d_in[0];
    const float* key   = (const float*)d_in[1];
    const float* value = (const float*)d_in[2];
    const float* bias  = (const float*)d_in[3];
    const int*   mask  = (const int*)d_in[4];
    const float* wq = (const float*)d_in[5];
    const float* bq = (const float*)d_in[6];
    const float* wk = (const float*)d_in[7];
    const float* bk = (const float*)d_in[8];
    const float* wv = (const float*)d_in[9];
    const float* bv = (const float*)d_in[10];
    const float* wo = (const float*)d_in[11];
    const float* bo = (const float*)d_in[12];
    float* out = (float*)d_out;

    cudaFuncSetAttribute(attn_tf32,
                         cudaFuncAttributeMaxDynamicSharedMemorySize, ATT_SMEM);
    cudaFuncSetAttribute(qkv_gemm,
                         cudaFuncAttributeMaxDynamicSharedMemorySize, GEMM_SMEM);
    cudaFuncSetAttribute(out_gemm,
                         cudaFuncAttributeMaxDynamicSharedMemorySize, GEMM_SMEM);

    prep_kernel<<<dim3(4096, 7), 256>>>(query, key, value, bias, wq, wk, wv, wo);
    qkv_gemm<<<dim3(HID / 128, MM / 128, 3), 256, GEMM_SMEM>>>(bq, bk, bv);
    attn_tf32<<<dim3(SS / 128, BB * NH), 128, ATT_SMEM>>>(mask);
    out_gemm<<<dim3(HID / 128, MM / 128), 256, GEMM_SMEM>>>(bo, out);
}

// round 12
// speedup vs baseline: 2.0264x; 1.0187x over previous
#include <cuda_runtime.h>
#include <cuda_bf16.h>
#include <math.h>

#define BB 2
#define SS 2048
#define HID 1024
#define NH 16
#define DK 64
#define MM (BB*SS)   // 4096

// ---------------------------------------------------------------------------
// Scratch
// ---------------------------------------------------------------------------
__device__ float g_q[BB*NH*SS*DK];   // [b,h,s,d]  tf32-rounded, pre-scaled 0.125
__device__ float g_k[BB*NH*SS*DK];   // tf32-rounded
__device__ float g_v[BB*NH*SS*DK];   // tf32-rounded
__device__ float g_x[BB*SS*HID];     // attn out [b,s,hid], tf32, k-PERMUTED

// tf32-prerounded + k-permuted operands for cp.async GEMMs
__device__ float c_q[MM*HID];
__device__ float c_k[MM*HID];
__device__ float c_v[MM*HID];
__device__ float c_wq[HID*HID];      // scaled by 0.125
__device__ float c_wk[HID*HID];
__device__ float c_wv[HID*HID];
__device__ float c_wo[HID*HID];

// ---------------------------------------------------------------------------
// tf32 helpers
// ---------------------------------------------------------------------------
__device__ __forceinline__ unsigned f2tf(float x) {
    unsigned u;
    asm("cvt.rna.tf32.f32 %0, %1;" : "=r"(u) : "f"(x));
    return u;
}
__device__ __forceinline__ float f2tff(float x) {
    return __uint_as_float(f2tf(x));
}

__device__ __forceinline__ void mma_tf32(float& c0, float& c1, float& c2, float& c3,
                                         unsigned a0, unsigned a1, unsigned a2, unsigned a3,
                                         unsigned b0, unsigned b1) {
    asm volatile(
        "mma.sync.aligned.m16n8k8.row.col.f32.tf32.tf32.f32 "
        "{%0,%1,%2,%3},{%4,%5,%6,%7},{%8,%9},{%0,%1,%2,%3};"
        : "+f"(c0), "+f"(c1), "+f"(c2), "+f"(c3)
        : "r"(a0), "r"(a1), "r"(a2), "r"(a3), "r"(b0), "r"(b1));
}

__device__ __forceinline__ void cpasync16(const float* dst_smem, const float* src) {
    unsigned d = (unsigned)__cvta_generic_to_shared(dst_smem);
    asm volatile("cp.async.cg.shared.global [%0], [%1], 16;\n" :: "r"(d), "l"(src));
}
__device__ __forceinline__ void cp_commit() {
    asm volatile("cp.async.commit_group;\n");
}
template<int N>
__device__ __forceinline__ void cp_wait() {
    asm volatile("cp.async.wait_group %0;\n" :: "n"(N));
}

// ---------------------------------------------------------------------------
// Precompute: tf32-round + k-permute (within-16: p=(k%4)*4+k/4, involution).
// k,v inputs scaled by (1+bias[row]); wq scaled by 0.125 (exact).
// ---------------------------------------------------------------------------
__global__ void __launch_bounds__(256)
prep_kernel(const float* __restrict__ query, const float* __restrict__ key,
            const float* __restrict__ value, const float* __restrict__ bias,
            const float* __restrict__ wq, const float* __restrict__ wk,
            const float* __restrict__ wv, const float* __restrict__ wo)
{
    const int y  = blockIdx.y;
    const int i4 = blockIdx.x * 256 + threadIdx.x;
    const int nEl = (y < 3) ? (MM * HID / 4) : (HID * HID / 4);
    if (i4 >= nEl) return;

    const float* src;
    float* dst;
    float s = 1.0f;
    if (y == 0)      { src = query; dst = c_q; }
    else if (y == 1) { src = key;   dst = c_k; s = 1.0f + bias[(i4 * 4) >> 10]; }
    else if (y == 2) { src = value; dst = c_v; s = 1.0f + bias[(i4 * 4) >> 10]; }
    else if (y == 3) { src = wq; dst = c_wq; s = 0.125f; }
    else if (y == 4) { src = wk; dst = c_wk; }
    else if (y == 5) { src = wv; dst = c_wv; }
    else             { src = wo; dst = c_wo; }

    float4 v = ((const float4*)src)[i4];
    int flat = i4 * 4;
    int blk  = flat & ~15;
    int a    = (flat >> 2) & 3;
    dst[blk + 0 * 4 + a] = f2tff(v.x * s);
    dst[blk + 1 * 4 + a] = f2tff(v.y * s);
    dst[blk + 2 * 4 + a] = f2tff(v.z * s);
    dst[blk + 3 * 4 + a] = f2tff(v.w * s);
}

// ---------------------------------------------------------------------------
// GEMM core: out = A[M,1024] @ W[1024,1024]^T + bias_scale*bias.
// A,W tf32 + k-permuted. cp.async 4-stage, smem [row][16], LDS.128 frags.
// ---------------------------------------------------------------------------
#define GST 16
#define NSTG 4
#define GEMM_SMEM (NSTG * 128 * GST * 2 * 4)   // 64 KB

__device__ __forceinline__ void gemm_core(
    const float* __restrict__ A,
    const float* __restrict__ W,
    const float* __restrict__ bias,
    float bias_scale,
    float* __restrict__ out,
    int transpose_out,
    int round_out,
    float* sm, int bm0, int bn0)
{
    float (*sA)[128][GST] = (float (*)[128][GST])sm;
    float (*sB)[128][GST] = (float (*)[128][GST])(sm + NSTG * 128 * GST);

    const int tid   = threadIdx.x;
    const int warp  = tid >> 5;
    const int lane  = tid & 31;
    const int g     = lane >> 2;
    const int q     = lane & 3;
    const int warpM = warp >> 2;
    const int warpN = warp & 3;

    const int lrow  = tid >> 1;
    const int lhalf = (tid & 1) * 8;

    const float* Ap = A + (size_t)(bm0 + lrow) * 1024 + lhalf;
    const float* Wp = W + (size_t)(bn0 + lrow) * 1024 + lhalf;

    #pragma unroll
    for (int s = 0; s < NSTG - 1; s++) {
        cpasync16(&sA[s][lrow][lhalf],     Ap + s * 16);
        cpasync16(&sA[s][lrow][lhalf + 4], Ap + s * 16 + 4);
        cpasync16(&sB[s][lrow][lhalf],     Wp + s * 16);
        cpasync16(&sB[s][lrow][lhalf + 4], Wp + s * 16 + 4);
        cp_commit();
    }

    float acc[4][4][4];
    #pragma unroll
    for (int mt = 0; mt < 4; mt++)
        #pragma unroll
        for (int nt = 0; nt < 4; nt++)
            #pragma unroll
            for (int i = 0; i < 4; i++) acc[mt][nt][i] = 0.0f;

    for (int kt = 0; kt < 64; kt++) {
        const int s = kt % NSTG;
        cp_wait<NSTG - 2>();
        __syncthreads();

        if (kt + NSTG - 1 < 64) {
            const int sn = (kt + NSTG - 1) % NSTG;
            const float* Ap2 = Ap + (kt + NSTG - 1) * 16;
            const float* Wp2 = Wp + (kt + NSTG - 1) * 16;
            cpasync16(&sA[sn][lrow][lhalf],     Ap2);
            cpasync16(&sA[sn][lrow][lhalf + 4], Ap2 + 4);
            cpasync16(&sB[sn][lrow][lhalf],     Wp2);
            cpasync16(&sB[sn][lrow][lhalf + 4], Wp2 + 4);
        }
        cp_commit();

        float4 Bf[4];
        #pragma unroll
        for (int nt = 0; nt < 4; nt++)
            Bf[nt] = *(const float4*)&sB[s][warpN * 32 + nt * 8 + g][4 * q];

        #pragma unroll
        for (int mt = 0; mt < 4; mt++) {
            int r = warpM * 64 + mt * 16 + g;
            float4 lo = *(const float4*)&sA[s][r][4 * q];
            float4 hi = *(const float4*)&sA[s][r + 8][4 * q];
            #pragma unroll
            for (int nt = 0; nt < 4; nt++) {
                mma_tf32(acc[mt][nt][0], acc[mt][nt][1], acc[mt][nt][2], acc[mt][nt][3],
                         __float_as_uint(lo.x), __float_as_uint(hi.x),
                         __float_as_uint(lo.y), __float_as_uint(hi.y),
                         __float_as_uint(Bf[nt].x), __float_as_uint(Bf[nt].y));
                mma_tf32(acc[mt][nt][0], acc[mt][nt][1], acc[mt][nt][2], acc[mt][nt][3],
                         __float_as_uint(lo.z), __float_as_uint(hi.z),
                         __float_as_uint(lo.w), __float_as_uint(hi.w),
                         __float_as_uint(Bf[nt].z), __float_as_uint(Bf[nt].w));
            }
        }
    }

    #pragma unroll
    for (int mt = 0; mt < 4; mt++) {
        #pragma unroll
        for (int nt = 0; nt < 4; nt++) {
            int col = bn0 + warpN * 32 + nt * 8 + 2 * q;
            float b0 = bias[col] * bias_scale, b1 = bias[col + 1] * bias_scale;
            #pragma unroll
            for (int half = 0; half < 2; half++) {
                int row = bm0 + warpM * 64 + mt * 16 + g + half * 8;
                float2 v;
                v.x = acc[mt][nt][half * 2 + 0] + b0;
                v.y = acc[mt][nt][half * 2 + 1] + b1;
                if (round_out) { v.x = f2tff(v.x); v.y = f2tff(v.y); }
                if (transpose_out) {
                    int bb = row >> 11, ss = row & 2047;
                    int hh = col >> 6, dd = col & 63;
                    *(float2*)&out[(((size_t)bb * NH + hh) * SS + ss) * DK + dd] = v;
                } else {
                    *(float2*)&out[(size_t)row * HID + col] = v;
                }
            }
        }
    }
}

__global__ void __launch_bounds__(256)
qkv_gemm(const float* __restrict__ bq,
         const float* __restrict__ bk,
         const float* __restrict__ bv)
{
    extern __shared__ float sm[];
    const int z = blockIdx.z;
    const float* A  = (z == 0) ? c_q  : (z == 1) ? c_k  : c_v;
    const float* W  = (z == 0) ? c_wq : (z == 1) ? c_wk : c_wv;
    const float* bb = (z == 0) ? bq   : (z == 1) ? bk   : bv;
    float* out      = (z == 0) ? g_q  : (z == 1) ? g_k  : g_v;
    float bsc       = (z == 0) ? 0.125f : 1.0f;
    gemm_core(A, W, bb, bsc, out, 1, 1, sm, blockIdx.y * 128, blockIdx.x * 128);
}

__global__ void __launch_bounds__(256)
out_gemm(const float* __restrict__ bo, float* __restrict__ out)
{
    extern __shared__ float sm[];
    gemm_core(g_x, c_wo, bo, 1.0f, out, 0, 0, sm, blockIdx.y * 128, blockIdx.x * 128);
}

// ---------------------------------------------------------------------------
// Flash attention, tf32 mma. Br=256 (8 warps x m32), Bc=64.
// K/V staged via cp.async double buffer (pure byte copy; operands pre-rounded).
// Smem (floats): Qt[64][264] Kt[2][64][68] Vt[2][64][72] Ps[256][68] mask[2048]
// ---------------------------------------------------------------------------
#define ATQ 264
#define ATK 68
#define ATV 72
#define ATP 68
#define ATT_SMEM ((64*ATQ + 2*64*ATK + 2*64*ATV + 256*ATP + SS) * 4)  // 212 KB

__global__ void __launch_bounds__(256)
attn_tf32(const int* __restrict__ mask)
{
    extern __shared__ float smf[];
    float* Qt    = smf;                  // [64][264]
    float* Kt    = Qt + 64 * ATQ;        // [2][64][68]
    float* Vt    = Kt + 2 * 64 * ATK;    // [2][64][72]
    float* Ps    = Vt + 2 * 64 * ATV;    // [256][68]
    float* maskF = Ps + 256 * ATP;       // [2048]

    const int tid  = threadIdx.x;
    const int warp = tid >> 5;    // 0..7
    const int lane = tid & 31;
    const int g    = lane >> 2;
    const int q    = lane & 3;
    const int rb   = warp * 32;

    const int bh = blockIdx.y;
    const int b  = bh >> 4;
    const int h  = bh & 15;
    const int q0 = blockIdx.x * 256;

    // Stage Q transposed (already tf32 + 0.125-scaled in g_q)
    const float* qptr = g_q + ((size_t)bh * SS + q0) * DK;
    for (int e = tid; e < 256 * 16; e += 256) {
        int r  = e >> 4;
        int d4 = (e & 15) << 2;
        float4 v = *(const float4*)(qptr + (size_t)r * DK + d4);
        Qt[(d4 + 0) * ATQ + r] = v.x;
        Qt[(d4 + 1) * ATQ + r] = v.y;
        Qt[(d4 + 2) * ATQ + r] = v.z;
        Qt[(d4 + 3) * ATQ + r] = v.w;
    }
    // Stage full mask row once
    for (int i = tid; i < SS; i += 256)
        maskF[i] = (mask[b * SS + i] == 0) ? 0.0f : 1.0f;

    const float* kbase = g_k + (size_t)bh * SS * DK;
    const float* vbase = g_v + (size_t)bh * SS * DK;

    // cp.async prologue: tile 0 -> buf 0
    #pragma unroll
    for (int e = tid; e < 64 * 16; e += 256) {
        int c  = e >> 4;
        int d4 = (e & 15) << 2;
        cpasync16(&Kt[0 * 64 * ATK + c * ATK + d4], kbase + (size_t)c * DK + d4);
        cpasync16(&Vt[0 * 64 * ATV + c * ATV + d4], vbase + (size_t)c * DK + d4);
    }
    cp_commit();

    float o[2][8][4];
    #pragma unroll
    for (int f = 0; f < 2; f++)
        #pragma unroll
        for (int nt = 0; nt < 8; nt++)
            #pragma unroll
            for (int i = 0; i < 4; i++) o[f][nt][i] = 0.0f;
    float mrow[4] = {-1e30f, -1e30f, -1e30f, -1e30f};
    float lrow[4] = {0.0f, 0.0f, 0.0f, 0.0f};

    for (int kt = 0; kt < SS / 64; kt++) {
        const int buf = kt & 1;

        // issue next tile into buf^1 (that buffer's readers finished last iter)
        if (kt + 1 < SS / 64) {
            const float* kp = kbase + (size_t)(kt + 1) * 64 * DK;
            const float* vp = vbase + (size_t)(kt + 1) * 64 * DK;
            #pragma unroll
            for (int e = tid; e < 64 * 16; e += 256) {
                int c  = e >> 4;
                int d4 = (e & 15) << 2;
                cpasync16(&Kt[(buf ^ 1) * 64 * ATK + c * ATK + d4], kp + (size_t)c * DK + d4);
                cpasync16(&Vt[(buf ^ 1) * 64 * ATV + c * ATV + d4], vp + (size_t)c * DK + d4);
            }
        }
        cp_commit();
        cp_wait<1>();          // tile kt complete
        __syncthreads();       // visible to all warps (also covers Qt/mask on kt=0)

        const float* Kb = Kt + buf * 64 * ATK;
        const float* Vb = Vt + buf * 64 * ATV;

        // ---- S = Q K^T ----
        float s[2][8][4];
        #pragma unroll
        for (int f = 0; f < 2; f++)
            #pragma unroll
            for (int nt = 0; nt < 8; nt++)
                #pragma unroll
                for (int i = 0; i < 4; i++) s[f][nt][i] = 0.0f;

        #pragma unroll
        for (int k8 = 0; k8 < 64; k8 += 8) {
            unsigned a[2][4];
            #pragma unroll
            for (int f = 0; f < 2; f++) {
                int r = rb + f * 16 + g;
                a[f][0] = __float_as_uint(Qt[(k8 + q) * ATQ + r]);
                a[f][1] = __float_as_uint(Qt[(k8 + q) * ATQ + r + 8]);
                a[f][2] = __float_as_uint(Qt[(k8 + 4 + q) * ATQ + r]);
                a[f][3] = __float_as_uint(Qt[(k8 + 4 + q) * ATQ + r + 8]);
            }
            #pragma unroll
            for (int nt = 0; nt < 8; nt++) {
                int c = nt * 8 + g;
                unsigned b0 = __float_as_uint(Kb[c * ATK + k8 + q]);
                unsigned b1 = __float_as_uint(Kb[c * ATK + k8 + 4 + q]);
                mma_tf32(s[0][nt][0], s[0][nt][1], s[0][nt][2], s[0][nt][3],
                         a[0][0], a[0][1], a[0][2], a[0][3], b0, b1);
                mma_tf32(s[1][nt][0], s[1][nt][1], s[1][nt][2], s[1][nt][3],
                         a[1][0], a[1][1], a[1][2], a[1][3], b0, b1);
            }
        }

        // ---- mask ----
        #pragma unroll
        for (int nt = 0; nt < 8; nt++) {
            float mk0 = maskF[kt * 64 + nt * 8 + 2 * q];
            float mk1 = maskF[kt * 64 + nt * 8 + 2 * q + 1];
            #pragma unroll
            for (int f = 0; f < 2; f++) {
                s[f][nt][0] = (mk0 == 0.0f) ? -10000.0f : s[f][nt][0];
                s[f][nt][2] = (mk0 == 0.0f) ? -10000.0f : s[f][nt][2];
                s[f][nt][1] = (mk1 == 0.0f) ? -10000.0f : s[f][nt][1];
                s[f][nt][3] = (mk1 == 0.0f) ? -10000.0f : s[f][nt][3];
            }
        }

        // ---- online softmax ----
        #pragma unroll
        for (int f = 0; f < 2; f++) {
            #pragma unroll
            for (int half = 0; half < 2; half++) {
                int ri = f * 2 + half;
                float mx = -1e30f;
                #pragma unroll
                for (int nt = 0; nt < 8; nt++) {
                    mx = fmaxf(mx, s[f][nt][half * 2 + 0]);
                    mx = fmaxf(mx, s[f][nt][half * 2 + 1]);
                }
                mx = fmaxf(mx, __shfl_xor_sync(0xffffffffu, mx, 1));
                mx = fmaxf(mx, __shfl_xor_sync(0xffffffffu, mx, 2));
                float mnew  = fmaxf(mrow[ri], mx);
                float alpha = __expf(mrow[ri] - mnew);
                float rs = 0.0f;
                #pragma unroll
                for (int nt = 0; nt < 8; nt++) {
                    float p0 = __expf(s[f][nt][half * 2 + 0] - mnew);
                    float p1 = __expf(s[f][nt][half * 2 + 1] - mnew);
                    s[f][nt][half * 2 + 0] = p0;
                    s[f][nt][half * 2 + 1] = p1;
                    rs += p0 + p1;
                }
                rs += __shfl_xor_sync(0xffffffffu, rs, 1);
                rs += __shfl_xor_sync(0xffffffffu, rs, 2);
                lrow[ri] = lrow[ri] * alpha + rs;
                mrow[ri] = mnew;
                #pragma unroll
                for (int nt = 0; nt < 8; nt++) {
                    o[f][nt][half * 2 + 0] *= alpha;
                    o[f][nt][half * 2 + 1] *= alpha;
                }
            }
        }

        // ---- stage P (tf32) in A layout ----
        #pragma unroll
        for (int f = 0; f < 2; f++) {
            int r = rb + f * 16 + g;
            #pragma unroll
            for (int nt = 0; nt < 8; nt++) {
                Ps[r * ATP + nt * 8 + 2 * q]           = f2tff(s[f][nt][0]);
                Ps[r * ATP + nt * 8 + 2 * q + 1]       = f2tff(s[f][nt][1]);
                Ps[(r + 8) * ATP + nt * 8 + 2 * q]     = f2tff(s[f][nt][2]);
                Ps[(r + 8) * ATP + nt * 8 + 2 * q + 1] = f2tff(s[f][nt][3]);
            }
        }
        __syncthreads();

        // ---- O += P V ----
        #pragma unroll
        for (int c8 = 0; c8 < 64; c8 += 8) {
            unsigned a[2][4];
            #pragma unroll
            for (int f = 0; f < 2; f++) {
                int r = rb + f * 16 + g;
                a[f][0] = __float_as_uint(Ps[r * ATP + c8 + q]);
                a[f][1] = __float_as_uint(Ps[(r + 8) * ATP + c8 + q]);
                a[f][2] = __float_as_uint(Ps[r * ATP + c8 + 4 + q]);
                a[f][3] = __float_as_uint(Ps[(r + 8) * ATP + c8 + 4 + q]);
            }
            #pragma unroll
            for (int nt = 0; nt < 8; nt++) {
                int d = nt * 8 + g;
                unsigned b0 = __float_as_uint(Vb[(c8 + q) * ATV + d]);
                unsigned b1 = __float_as_uint(Vb[(c8 + 4 + q) * ATV + d]);
                mma_tf32(o[0][nt][0], o[0][nt][1], o[0][nt][2], o[0][nt][3],
                         a[0][0], a[0][1], a[0][2], a[0][3], b0, b1);
                mma_tf32(o[1][nt][0], o[1][nt][1], o[1][nt][2], o[1][nt][3],
                         a[1][0], a[1][1], a[1][2], a[1][3], b0, b1);
            }
        }
        __syncthreads();   // all warps done with Kb/Vb/Ps before next issue/store
    }

    // Epilogue: normalize, tf32-round, write g_x with k-permuted columns
    #pragma unroll
    for (int f = 0; f < 2; f++) {
        float inv0 = 1.0f / lrow[f * 2 + 0];
        float inv1 = 1.0f / lrow[f * 2 + 1];
        #pragma unroll
        for (int nt = 0; nt < 8; nt++) {
            int w0  = nt * 8 + 2 * q;
            int blk = w0 & ~15;
            int wa  = w0 & 15;
            int wb  = wa + 1;
            int pa  = ((wa & 3) << 2) | (wa >> 2);
            int pb  = ((wb & 3) << 2) | (wb >> 2);
            int base = h * DK + blk;
            int rowA = q0 + rb + f * 16 + g;
            int rowB = rowA + 8;
            size_t offA = ((size_t)b * SS + rowA) * HID + base;
            size_t offB = ((size_t)b * SS + rowB) * HID + base;
            g_x[offA + pa] = f2tff(o[f][nt][0] * inv0);
            g_x[offA + pb] = f2tff(o[f][nt][1] * inv0);
            g_x[offB + pa] = f2tff(o[f][nt][2] * inv1);
            g_x[offB + pb] = f2tff(o[f][nt][3] * inv1);
        }
    }
}

// ---------------------------------------------------------------------------
extern "C" void kernel_launch(void* const* d_in, const int* in_sizes, int n_in,
                              void* d_out, int out_size)
{
    const float* query = (const float*)d_in[0];
    const float* key   = (const float*)d_in[1];
    const float* value = (const float*)d_in[2];
    const float* bias  = (const float*)d_in[3];
    const int*   mask  = (const int*)d_in[4];
    const float* wq = (const float*)d_in[5];
    const float* bq = (const float*)d_in[6];
    const float* wk = (const float*)d_in[7];
    const float* bk = (const float*)d_in[8];
    const float* wv = (const float*)d_in[9];
    const float* bv = (const float*)d_in[10];
    const float* wo = (const float*)d_in[11];
    const float* bo = (const float*)d_in[12];
    float* out = (float*)d_out;

    cudaFuncSetAttribute(attn_tf32,
                         cudaFuncAttributeMaxDynamicSharedMemorySize, ATT_SMEM);
    cudaFuncSetAttribute(qkv_gemm,
                         cudaFuncAttributeMaxDynamicSharedMemorySize, GEMM_SMEM);
    cudaFuncSetAttribute(out_gemm,
                         cudaFuncAttributeMaxDynamicSharedMemorySize, GEMM_SMEM);

    prep_kernel<<<dim3(4096, 7), 256>>>(query, key, value, bias, wq, wk, wv, wo);
    qkv_gemm<<<dim3(HID / 128, MM / 128, 3), 256, GEMM_SMEM>>>(bq, bk, bv);
    attn_tf32<<<dim3(SS / 256, BB * NH), 256, ATT_SMEM>>>(mask);
    out_gemm<<<dim3(HID / 128, MM / 128), 256, GEMM_SMEM>>>(bo, out);
}

// round 15
// speedup vs baseline: 2.0483x; 1.0108x over previous
#include <cuda_runtime.h>
#include <cuda_bf16.h>
#include <math.h>

#define BB 2
#define SS 2048
#define HID 1024
#define NH 16
#define DK 64
#define MM (BB*SS)   // 4096

// ---------------------------------------------------------------------------
// Scratch
// ---------------------------------------------------------------------------
__device__ float g_q[BB*NH*SS*DK];   // [b,h,s,d]  tf32-rounded, pre-scaled 0.125
__device__ float g_k[BB*NH*SS*DK];   // tf32-rounded
__device__ float g_v[BB*NH*SS*DK];   // tf32-rounded
__device__ float g_x[BB*SS*HID];     // attn out [b,s,hid], tf32, k-PERMUTED

// tf32-prerounded + k-permuted operands for cp.async GEMMs
__device__ float c_q[MM*HID];
__device__ float c_k[MM*HID];
__device__ float c_v[MM*HID];
__device__ float c_wq[HID*HID];      // scaled by 0.125
__device__ float c_wk[HID*HID];
__device__ float c_wv[HID*HID];
__device__ float c_wo[HID*HID];

// ---------------------------------------------------------------------------
// tf32 helpers
// ---------------------------------------------------------------------------
__device__ __forceinline__ unsigned f2tf(float x) {
    unsigned u;
    asm("cvt.rna.tf32.f32 %0, %1;" : "=r"(u) : "f"(x));
    return u;
}
__device__ __forceinline__ float f2tff(float x) {
    return __uint_as_float(f2tf(x));
}

__device__ __forceinline__ void mma_tf32(float& c0, float& c1, float& c2, float& c3,
                                         unsigned a0, unsigned a1, unsigned a2, unsigned a3,
                                         unsigned b0, unsigned b1) {
    asm volatile(
        "mma.sync.aligned.m16n8k8.row.col.f32.tf32.tf32.f32 "
        "{%0,%1,%2,%3},{%4,%5,%6,%7},{%8,%9},{%0,%1,%2,%3};"
        : "+f"(c0), "+f"(c1), "+f"(c2), "+f"(c3)
        : "r"(a0), "r"(a1), "r"(a2), "r"(a3), "r"(b0), "r"(b1));
}

__device__ __forceinline__ void cpasync16(const float* dst_smem, const float* src) {
    unsigned d = (unsigned)__cvta_generic_to_shared(dst_smem);
    asm volatile("cp.async.cg.shared.global [%0], [%1], 16;\n" :: "r"(d), "l"(src));
}
__device__ __forceinline__ void cp_commit() {
    asm volatile("cp.async.commit_group;\n");
}
template<int N>
__device__ __forceinline__ void cp_wait() {
    asm volatile("cp.async.wait_group %0;\n" :: "n"(N));
}

// ---------------------------------------------------------------------------
// Precompute: tf32-round + k-permute (within-16: p=(k%4)*4+k/4, involution).
// k,v inputs scaled by (1+bias[row]); wq scaled by 0.125 (exact).
// ---------------------------------------------------------------------------
__global__ void __launch_bounds__(256)
prep_kernel(const float* __restrict__ query, const float* __restrict__ key,
            const float* __restrict__ value, const float* __restrict__ bias,
            const float* __restrict__ wq, const float* __restrict__ wk,
            const float* __restrict__ wv, const float* __restrict__ wo)
{
    const int y  = blockIdx.y;
    const int i4 = blockIdx.x * 256 + threadIdx.x;
    const int nEl = (y < 3) ? (MM * HID / 4) : (HID * HID / 4);
    if (i4 >= nEl) return;

    const float* src;
    float* dst;
    float s = 1.0f;
    if (y == 0)      { src = query; dst = c_q; }
    else if (y == 1) { src = key;   dst = c_k; s = 1.0f + bias[(i4 * 4) >> 10]; }
    else if (y == 2) { src = value; dst = c_v; s = 1.0f + bias[(i4 * 4) >> 10]; }
    else if (y == 3) { src = wq; dst = c_wq; s = 0.125f; }
    else if (y == 4) { src = wk; dst = c_wk; }
    else if (y == 5) { src = wv; dst = c_wv; }
    else             { src = wo; dst = c_wo; }

    float4 v = ((const float4*)src)[i4];
    int flat = i4 * 4;
    int blk  = flat & ~15;
    int a    = (flat >> 2) & 3;
    dst[blk + 0 * 4 + a] = f2tff(v.x * s);
    dst[blk + 1 * 4 + a] = f2tff(v.y * s);
    dst[blk + 2 * 4 + a] = f2tff(v.z * s);
    dst[blk + 3 * 4 + a] = f2tff(v.w * s);
}

// ---------------------------------------------------------------------------
// GEMM core: out = A[M,1024] @ W[1024,1024]^T + bias_scale*bias.
// A,W tf32 + k-permuted. CTA tile 128x256, 8 warps, warp tile 64x64.
// cp.async 4-stage, smem [row][16], LDS.128 frags (conflict-free).
// Per warp per k16: 16 LDS.128 + 64 MMA.
// ---------------------------------------------------------------------------
#define GST 16
#define NSTG 4
#define GBM 128
#define GBN 256
#define GEMM_SMEM (NSTG * (GBM + GBN) * GST * 4)   // 96 KB

__device__ __forceinline__ void gemm_core(
    const float* __restrict__ A,
    const float* __restrict__ W,
    const float* __restrict__ bias,
    float bias_scale,
    float* __restrict__ out,
    int transpose_out,
    int round_out,
    float* sm, int bm0, int bn0)
{
    float (*sA)[GBM][GST] = (float (*)[GBM][GST])sm;
    float (*sB)[GBN][GST] = (float (*)[GBN][GST])(sm + NSTG * GBM * GST);

    const int tid   = threadIdx.x;
    const int warp  = tid >> 5;
    const int lane  = tid & 31;
    const int g     = lane >> 2;
    const int q     = lane & 3;
    const int warpM = warp >> 2;    // 0..1  (m 64 each)
    const int warpN = warp & 3;     // 0..3  (n 64 each)

    const int lrow  = tid >> 1;          // 0..127
    const int lhalf = (tid & 1) * 8;     // 0 or 8 floats

    const float* Ap  = A + (size_t)(bm0 + lrow) * 1024 + lhalf;
    const float* Wp0 = W + (size_t)(bn0 + lrow) * 1024 + lhalf;
    const float* Wp1 = Wp0 + (size_t)128 * 1024;

    #pragma unroll
    for (int s = 0; s < NSTG - 1; s++) {
        cpasync16(&sA[s][lrow][lhalf],           Ap  + s * 16);
        cpasync16(&sA[s][lrow][lhalf + 4],       Ap  + s * 16 + 4);
        cpasync16(&sB[s][lrow][lhalf],           Wp0 + s * 16);
        cpasync16(&sB[s][lrow][lhalf + 4],       Wp0 + s * 16 + 4);
        cpasync16(&sB[s][lrow + 128][lhalf],     Wp1 + s * 16);
        cpasync16(&sB[s][lrow + 128][lhalf + 4], Wp1 + s * 16 + 4);
        cp_commit();
    }

    float acc[4][8][4];
    #pragma unroll
    for (int mt = 0; mt < 4; mt++)
        #pragma unroll
        for (int nt = 0; nt < 8; nt++)
            #pragma unroll
            for (int i = 0; i < 4; i++) acc[mt][nt][i] = 0.0f;

    for (int kt = 0; kt < 64; kt++) {
        const int s = kt % NSTG;
        cp_wait<NSTG - 2>();
        __syncthreads();

        if (kt + NSTG - 1 < 64) {
            const int sn = (kt + NSTG - 1) % NSTG;
            const int ko = (kt + NSTG - 1) * 16;
            cpasync16(&sA[sn][lrow][lhalf],           Ap  + ko);
            cpasync16(&sA[sn][lrow][lhalf + 4],       Ap  + ko + 4);
            cpasync16(&sB[sn][lrow][lhalf],           Wp0 + ko);
            cpasync16(&sB[sn][lrow][lhalf + 4],       Wp0 + ko + 4);
            cpasync16(&sB[sn][lrow + 128][lhalf],     Wp1 + ko);
            cpasync16(&sB[sn][lrow + 128][lhalf + 4], Wp1 + ko + 4);
        }
        cp_commit();

        float4 Bf[8];
        #pragma unroll
        for (int nt = 0; nt < 8; nt++)
            Bf[nt] = *(const float4*)&sB[s][warpN * 64 + nt * 8 + g][4 * q];

        #pragma unroll
        for (int mt = 0; mt < 4; mt++) {
            int r = warpM * 64 + mt * 16 + g;
            float4 lo = *(const float4*)&sA[s][r][4 * q];
            float4 hi = *(const float4*)&sA[s][r + 8][4 * q];
            #pragma unroll
            for (int nt = 0; nt < 8; nt++) {
                mma_tf32(acc[mt][nt][0], acc[mt][nt][1], acc[mt][nt][2], acc[mt][nt][3],
                         __float_as_uint(lo.x), __float_as_uint(hi.x),
                         __float_as_uint(lo.y), __float_as_uint(hi.y),
                         __float_as_uint(Bf[nt].x), __float_as_uint(Bf[nt].y));
                mma_tf32(acc[mt][nt][0], acc[mt][nt][1], acc[mt][nt][2], acc[mt][nt][3],
                         __float_as_uint(lo.z), __float_as_uint(hi.z),
                         __float_as_uint(lo.w), __float_as_uint(hi.w),
                         __float_as_uint(Bf[nt].z), __float_as_uint(Bf[nt].w));
            }
        }
    }

    #pragma unroll
    for (int mt = 0; mt < 4; mt++) {
        #pragma unroll
        for (int nt = 0; nt < 8; nt++) {
            int col = bn0 + warpN * 64 + nt * 8 + 2 * q;
            float b0 = bias[col] * bias_scale, b1 = bias[col + 1] * bias_scale;
            #pragma unroll
            for (int half = 0; half < 2; half++) {
                int row = bm0 + warpM * 64 + mt * 16 + g + half * 8;
                float2 v;
                v.x = acc[mt][nt][half * 2 + 0] + b0;
                v.y = acc[mt][nt][half * 2 + 1] + b1;
                if (round_out) { v.x = f2tff(v.x); v.y = f2tff(v.y); }
                if (transpose_out) {
                    int bb = row >> 11, ss = row & 2047;
                    int hh = col >> 6, dd = col & 63;
                    *(float2*)&out[(((size_t)bb * NH + hh) * SS + ss) * DK + dd] = v;
                } else {
                    *(float2*)&out[(size_t)row * HID + col] = v;
                }
            }
        }
    }
}

__global__ void __launch_bounds__(256)
qkv_gemm(const float* __restrict__ bq,
         const float* __restrict__ bk,
         const float* __restrict__ bv)
{
    extern __shared__ float sm[];
    const int z = blockIdx.z;
    const float* A  = (z == 0) ? c_q  : (z == 1) ? c_k  : c_v;
    const float* W  = (z == 0) ? c_wq : (z == 1) ? c_wk : c_wv;
    const float* bb = (z == 0) ? bq   : (z == 1) ? bk   : bv;
    float* out      = (z == 0) ? g_q  : (z == 1) ? g_k  : g_v;
    float bsc       = (z == 0) ? 0.125f : 1.0f;
    gemm_core(A, W, bb, bsc, out, 1, 1, sm, blockIdx.y * GBM, blockIdx.x * GBN);
}

__global__ void __launch_bounds__(256)
out_gemm(const float* __restrict__ bo, float* __restrict__ out)
{
    extern __shared__ float sm[];
    gemm_core(g_x, c_wo, bo, 1.0f, out, 0, 0, sm, blockIdx.y * GBM, blockIdx.x * GBN);
}

// ---------------------------------------------------------------------------
// Flash attention, tf32 mma. Br=256 (8 warps x m32), Bc=64. (unchanged R12)
// ---------------------------------------------------------------------------
#define ATQ 264
#define ATK 68
#define ATV 72
#define ATP 68
#define ATT_SMEM ((64*ATQ + 2*64*ATK + 2*64*ATV + 256*ATP + SS) * 4)  // 212 KB

__global__ void __launch_bounds__(256)
attn_tf32(const int* __restrict__ mask)
{
    extern __shared__ float smf[];
    float* Qt    = smf;                  // [64][264]
    float* Kt    = Qt + 64 * ATQ;        // [2][64][68]
    float* Vt    = Kt + 2 * 64 * ATK;    // [2][64][72]
    float* Ps    = Vt + 2 * 64 * ATV;    // [256][68]
    float* maskF = Ps + 256 * ATP;       // [2048]

    const int tid  = threadIdx.x;
    const int warp = tid >> 5;
    const int lane = tid & 31;
    const int g    = lane >> 2;
    const int q    = lane & 3;
    const int rb   = warp * 32;

    const int bh = blockIdx.y;
    const int b  = bh >> 4;
    const int h  = bh & 15;
    const int q0 = blockIdx.x * 256;

    const float* qptr = g_q + ((size_t)bh * SS + q0) * DK;
    for (int e = tid; e < 256 * 16; e += 256) {
        int r  = e >> 4;
        int d4 = (e & 15) << 2;
        float4 v = *(const float4*)(qptr + (size_t)r * DK + d4);
        Qt[(d4 + 0) * ATQ + r] = v.x;
        Qt[(d4 + 1) * ATQ + r] = v.y;
        Qt[(d4 + 2) * ATQ + r] = v.z;
        Qt[(d4 + 3) * ATQ + r] = v.w;
    }
    for (int i = tid; i < SS; i += 256)
        maskF[i] = (mask[b * SS + i] == 0) ? 0.0f : 1.0f;

    const float* kbase = g_k + (size_t)bh * SS * DK;
    const float* vbase = g_v + (size_t)bh * SS * DK;

    #pragma unroll
    for (int e = tid; e < 64 * 16; e += 256) {
        int c  = e >> 4;
        int d4 = (e & 15) << 2;
        cpasync16(&Kt[0 * 64 * ATK + c * ATK + d4], kbase + (size_t)c * DK + d4);
        cpasync16(&Vt[0 * 64 * ATV + c * ATV + d4], vbase + (size_t)c * DK + d4);
    }
    cp_commit();

    float o[2][8][4];
    #pragma unroll
    for (int f = 0; f < 2; f++)
        #pragma unroll
        for (int nt = 0; nt < 8; nt++)
            #pragma unroll
            for (int i = 0; i < 4; i++) o[f][nt][i] = 0.0f;
    float mrow[4] = {-1e30f, -1e30f, -1e30f, -1e30f};
    float lrow[4] = {0.0f, 0.0f, 0.0f, 0.0f};

    for (int kt = 0; kt < SS / 64; kt++) {
        const int buf = kt & 1;

        if (kt + 1 < SS / 64) {
            const float* kp = kbase + (size_t)(kt + 1) * 64 * DK;
            const float* vp = vbase + (size_t)(kt + 1) * 64 * DK;
            #pragma unroll
            for (int e = tid; e < 64 * 16; e += 256) {
                int c  = e >> 4;
                int d4 = (e & 15) << 2;
                cpasync16(&Kt[(buf ^ 1) * 64 * ATK + c * ATK + d4], kp + (size_t)c * DK + d4);
                cpasync16(&Vt[(buf ^ 1) * 64 * ATV + c * ATV + d4], vp + (size_t)c * DK + d4);
            }
        }
        cp_commit();
        cp_wait<1>();
        __syncthreads();

        const float* Kb = Kt + buf * 64 * ATK;
        const float* Vb = Vt + buf * 64 * ATV;

        float s[2][8][4];
        #pragma unroll
        for (int f = 0; f < 2; f++)
            #pragma unroll
            for (int nt = 0; nt < 8; nt++)
                #pragma unroll
                for (int i = 0; i < 4; i++) s[f][nt][i] = 0.0f;

        #pragma unroll
        for (int k8 = 0; k8 < 64; k8 += 8) {
            unsigned a[2][4];
            #pragma unroll
            for (int f = 0; f < 2; f++) {
                int r = rb + f * 16 + g;
                a[f][0] = __float_as_uint(Qt[(k8 + q) * ATQ + r]);
                a[f][1] = __float_as_uint(Qt[(k8 + q) * ATQ + r + 8]);
                a[f][2] = __float_as_uint(Qt[(k8 + 4 + q) * ATQ + r]);
                a[f][3] = __float_as_uint(Qt[(k8 + 4 + q) * ATQ + r + 8]);
            }
            #pragma unroll
            for (int nt = 0; nt < 8; nt++) {
                int c = nt * 8 + g;
                unsigned b0 = __float_as_uint(Kb[c * ATK + k8 + q]);
                unsigned b1 = __float_as_uint(Kb[c * ATK + k8 + 4 + q]);
                mma_tf32(s[0][nt][0], s[0][nt][1], s[0][nt][2], s[0][nt][3],
                         a[0][0], a[0][1], a[0][2], a[0][3], b0, b1);
                mma_tf32(s[1][nt][0], s[1][nt][1], s[1][nt][2], s[1][nt][3],
                         a[1][0], a[1][1], a[1][2], a[1][3], b0, b1);
            }
        }

        #pragma unroll
        for (int nt = 0; nt < 8; nt++) {
            float mk0 = maskF[kt * 64 + nt * 8 + 2 * q];
            float mk1 = maskF[kt * 64 + nt * 8 + 2 * q + 1];
            #pragma unroll
            for (int f = 0; f < 2; f++) {
                s[f][nt][0] = (mk0 == 0.0f) ? -10000.0f : s[f][nt][0];
                s[f][nt][2] = (mk0 == 0.0f) ? -10000.0f : s[f][nt][2];
                s[f][nt][1] = (mk1 == 0.0f) ? -10000.0f : s[f][nt][1];
                s[f][nt][3] = (mk1 == 0.0f) ? -10000.0f : s[f][nt][3];
            }
        }

        #pragma unroll
        for (int f = 0; f < 2; f++) {
            #pragma unroll
            for (int half = 0; half < 2; half++) {
                int ri = f * 2 + half;
                float mx = -1e30f;
                #pragma unroll
                for (int nt = 0; nt < 8; nt++) {
                    mx = fmaxf(mx, s[f][nt][half * 2 + 0]);
                    mx = fmaxf(mx, s[f][nt][half * 2 + 1]);
                }
                mx = fmaxf(mx, __shfl_xor_sync(0xffffffffu, mx, 1));
                mx = fmaxf(mx, __shfl_xor_sync(0xffffffffu, mx, 2));
                float mnew  = fmaxf(mrow[ri], mx);
                float alpha = __expf(mrow[ri] - mnew);
                float rs = 0.0f;
                #pragma unroll
                for (int nt = 0; nt < 8; nt++) {
                    float p0 = __expf(s[f][nt][half * 2 + 0] - mnew);
                    float p1 = __expf(s[f][nt][half * 2 + 1] - mnew);
                    s[f][nt][half * 2 + 0] = p0;
                    s[f][nt][half * 2 + 1] = p1;
                    rs += p0 + p1;
                }
                rs += __shfl_xor_sync(0xffffffffu, rs, 1);
                rs += __shfl_xor_sync(0xffffffffu, rs, 2);
                lrow[ri] = lrow[ri] * alpha + rs;
                mrow[ri] = mnew;
                #pragma unroll
                for (int nt = 0; nt < 8; nt++) {
                    o[f][nt][half * 2 + 0] *= alpha;
                    o[f][nt][half * 2 + 1] *= alpha;
                }
            }
        }

        #pragma unroll
        for (int f = 0; f < 2; f++) {
            int r = rb + f * 16 + g;
            #pragma unroll
            for (int nt = 0; nt < 8; nt++) {
                Ps[r * ATP + nt * 8 + 2 * q]           = f2tff(s[f][nt][0]);
                Ps[r * ATP + nt * 8 + 2 * q + 1]       = f2tff(s[f][nt][1]);
                Ps[(r + 8) * ATP + nt * 8 + 2 * q]     = f2tff(s[f][nt][2]);
                Ps[(r + 8) * ATP + nt * 8 + 2 * q + 1] = f2tff(s[f][nt][3]);
            }
        }
        __syncthreads();

        #pragma unroll
        for (int c8 = 0; c8 < 64; c8 += 8) {
            unsigned a[2][4];
            #pragma unroll
            for (int f = 0; f < 2; f++) {
                int r = rb + f * 16 + g;
                a[f][0] = __float_as_uint(Ps[r * ATP + c8 + q]);
                a[f][1] = __float_as_uint(Ps[(r + 8) * ATP + c8 + q]);
                a[f][2] = __float_as_uint(Ps[r * ATP + c8 + 4 + q]);
                a[f][3] = __float_as_uint(Ps[(r + 8) * ATP + c8 + 4 + q]);
            }
            #pragma unroll
            for (int nt = 0; nt < 8; nt++) {
                int d = nt * 8 + g;
                unsigned b0 = __float_as_uint(Vb[(c8 + q) * ATV + d]);
                unsigned b1 = __float_as_uint(Vb[(c8 + 4 + q) * ATV + d]);
                mma_tf32(o[0][nt][0], o[0][nt][1], o[0][nt][2], o[0][nt][3],
                         a[0][0], a[0][1], a[0][2], a[0][3], b0, b1);
                mma_tf32(o[1][nt][0], o[1][nt][1], o[1][nt][2], o[1][nt][3],
                         a[1][0], a[1][1], a[1][2], a[1][3], b0, b1);
            }
        }
        __syncthreads();
    }

    #pragma unroll
    for (int f = 0; f < 2; f++) {
        float inv0 = 1.0f / lrow[f * 2 + 0];
        float inv1 = 1.0f / lrow[f * 2 + 1];
        #pragma unroll
        for (int nt = 0; nt < 8; nt++) {
            int w0  = nt * 8 + 2 * q;
            int blk = w0 & ~15;
            int wa  = w0 & 15;
            int wb  = wa + 1;
            int pa  = ((wa & 3) << 2) | (wa >> 2);
            int pb  = ((wb & 3) << 2) | (wb >> 2);
            int base = h * DK + blk;
            int rowA = q0 + rb + f * 16 + g;
            int rowB = rowA + 8;
            size_t offA = ((size_t)b * SS + rowA) * HID + base;
            size_t offB = ((size_t)b * SS + rowB) * HID + base;
            g_x[offA + pa] = f2tff(o[f][nt][0] * inv0);
            g_x[offA + pb] = f2tff(o[f][nt][1] * inv0);
            g_x[offB + pa] = f2tff(o[f][nt][2] * inv1);
            g_x[offB + pb] = f2tff(o[f][nt][3] * inv1);
        }
    }
}

// ---------------------------------------------------------------------------
extern "C" void kernel_launch(void* const* d_in, const int* in_sizes, int n_in,
                              void* d_out, int out_size)
{
    const float* query = (const float*)d_in[0];
    const float* key   = (const float*)d_in[1];
    const float* value = (const float*)d_in[2];
    const float* bias  = (const float*)d_in[3];
    const int*   mask  = (const int*)d_in[4];
    const float* wq = (const float*)d_in[5];
    const float* bq = (const float*)d_in[6];
    const float* wk = (const float*)d_in[7];
    const float* bk = (const float*)d_in[8];
    const float* wv = (const float*)d_in[9];
    const float* bv = (const float*)d_in[10];
    const float* wo = (const float*)d_in[11];
    const float* bo = (const float*)d_in[12];
    float* out = (float*)d_out;

    cudaFuncSetAttribute(attn_tf32,
                         cudaFuncAttributeMaxDynamicSharedMemorySize, ATT_SMEM);
    cudaFuncSetAttribute(qkv_gemm,
                         cudaFuncAttributeMaxDynamicSharedMemorySize, GEMM_SMEM);
    cudaFuncSetAttribute(out_gemm,
                         cudaFuncAttributeMaxDynamicSharedMemorySize, GEMM_SMEM);

    prep_kernel<<<dim3(4096, 7), 256>>>(query, key, value, bias, wq, wk, wv, wo);
    qkv_gemm<<<dim3(HID / GBN, MM / GBM, 3), 256, GEMM_SMEM>>>(bq, bk, bv);
    attn_tf32<<<dim3(SS / 256, BB * NH), 256, ATT_SMEM>>>(mask);
    out_gemm<<<dim3(HID / GBN, MM / GBM), 256, GEMM_SMEM>>>(bo, out);
}

// round 16
// speedup vs baseline: 2.9151x; 1.4232x over previous
#include <cuda_runtime.h>
#include <cuda_fp16.h>
#include <math.h>

#define BB 2
#define SS 2048
#define HID 1024
#define NH 16
#define DK 64
#define MM (BB*SS)   // 4096

// ---------------------------------------------------------------------------
// Scratch (fp16 operands, 32-block k-permuted where noted)
// ---------------------------------------------------------------------------
__device__ __half g_q[BB*NH*SS*DK];   // [b,h,s,d-perm], pre-scaled 0.125
__device__ __half g_k[BB*NH*SS*DK];   // [b,h,s,d-perm]
__device__ __half g_v[BB*NH*SS*DK];   // [b,h,d,s-perm]  (TRANSPOSED)
__device__ __half g_x[BB*SS*HID];     // [b,s,hid-perm]  attn out

__device__ __half c_q[MM*HID];        // k-permuted fp16 GEMM operands
__device__ __half c_k[MM*HID];
__device__ __half c_v[MM*HID];
__device__ __half c_wq[HID*HID];      // scaled by 0.125
__device__ __half c_wk[HID*HID];
__device__ __half c_wv[HID*HID];
__device__ __half c_wo[HID*HID];

// ---------------------------------------------------------------------------
// helpers
// ---------------------------------------------------------------------------
__device__ __forceinline__ unsigned packh2(float lo, float hi) {
    unsigned u;
    asm("cvt.rn.f16x2.f32 %0, %1, %2;" : "=r"(u) : "f"(hi), "f"(lo));
    return u;
}

__device__ __forceinline__ void mma_f16(float& c0, float& c1, float& c2, float& c3,
                                        unsigned a0, unsigned a1, unsigned a2, unsigned a3,
                                        unsigned b0, unsigned b1) {
    asm volatile(
        "mma.sync.aligned.m16n8k16.row.col.f32.f16.f16.f32 "
        "{%0,%1,%2,%3},{%4,%5,%6,%7},{%8,%9},{%0,%1,%2,%3};"
        : "+f"(c0), "+f"(c1), "+f"(c2), "+f"(c3)
        : "r"(a0), "r"(a1), "r"(a2), "r"(a3), "r"(b0), "r"(b1));
}

__device__ __forceinline__ void cpasync16(const void* dst_smem, const void* src) {
    unsigned d = (unsigned)__cvta_generic_to_shared(dst_smem);
    asm volatile("cp.async.cg.shared.global [%0], [%1], 16;\n" :: "r"(d), "l"(src));
}
__device__ __forceinline__ void cp_commit() {
    asm volatile("cp.async.commit_group;\n");
}
template<int N>
__device__ __forceinline__ void cp_wait() {
    asm volatile("cp.async.wait_group %0;\n" :: "n"(N));
}

// permute within a 32-block (even index o): position of pair (o,o+1)
__device__ __forceinline__ int perm32_pair(int o) {
    return 8 * ((o >> 1) & 3) + 4 * ((o >> 4) & 1) + 2 * ((o >> 3) & 1);
}
// full permute (any index)
__device__ __forceinline__ int perm32(int o) {
    return 8 * ((o >> 1) & 3) + 4 * ((o >> 4) & 1) + 2 * ((o >> 3) & 1) + (o & 1);
}

// ---------------------------------------------------------------------------
// Precompute: fp32 -> fp16 with 32-block k-permute.
// k,v inputs scaled by (1+bias[row]); wq scaled by 0.125.
// ---------------------------------------------------------------------------
__global__ void __launch_bounds__(256)
prep_kernel(const float* __restrict__ query, const float* __restrict__ key,
            const float* __restrict__ value, const float* __restrict__ bias,
            const float* __restrict__ wq, const float* __restrict__ wk,
            const float* __restrict__ wv, const float* __restrict__ wo)
{
    const int y  = blockIdx.y;
    const int i4 = blockIdx.x * 256 + threadIdx.x;
    const int nEl = (y < 3) ? (MM * HID / 4) : (HID * HID / 4);
    if (i4 >= nEl) return;

    const float* src;
    __half* dst;
    float s = 1.0f;
    if (y == 0)      { src = query; dst = c_q; }
    else if (y == 1) { src = key;   dst = c_k; s = 1.0f + bias[(i4 * 4) >> 10]; }
    else if (y == 2) { src = value; dst = c_v; s = 1.0f + bias[(i4 * 4) >> 10]; }
    else if (y == 3) { src = wq; dst = c_wq; s = 0.125f; }
    else if (y == 4) { src = wk; dst = c_wk; }
    else if (y == 5) { src = wv; dst = c_wv; }
    else             { src = wo; dst = c_wo; }

    float4 v = ((const float4*)src)[i4];
    int flat = i4 * 4;
    int base = flat & ~31;
    int o    = flat & 31;            // even, multiple of 4
    int np0  = perm32_pair(o);
    int np1  = perm32_pair(o + 2);
    *(unsigned*)&dst[base + np0] = packh2(v.x * s, v.y * s);
    *(unsigned*)&dst[base + np1] = packh2(v.z * s, v.w * s);
}

// ---------------------------------------------------------------------------
// fp16 GEMM: out = A[M,1024] @ W[1024,1024]^T + bias_scale*bias.
// CTA 128x256, 8 warps, warp tile 64x64, BK=32, cp.async 4-stage.
// Smem rows 32 halves (64B) -> LDS.128 frags conflict-free, no padding.
// out_mode: 0 = fp32 [row][col]; 1 = fp16 [b,h,s,d-perm]; 2 = fp16 [b,h,d,s-perm]
// ---------------------------------------------------------------------------
#define GKH 32
#define NSTG 4
#define GBM 128
#define GBN 256
#define GEMM_SMEM (NSTG * (GBM + GBN) * GKH * 2)   // 96 KB

__device__ __forceinline__ void gemm_core(
    const __half* __restrict__ A,
    const __half* __restrict__ W,
    const float* __restrict__ bias,
    float bias_scale,
    float* __restrict__ outf,
    __half* __restrict__ outh,
    int out_mode,
    __half* sm, int bm0, int bn0)
{
    __half (*sA)[GBM][GKH] = (__half (*)[GBM][GKH])sm;
    __half (*sB)[GBN][GKH] = (__half (*)[GBN][GKH])(sm + NSTG * GBM * GKH);

    const int tid   = threadIdx.x;
    const int warp  = tid >> 5;
    const int lane  = tid & 31;
    const int g     = lane >> 2;
    const int q     = lane & 3;
    const int warpM = warp >> 2;    // 0..1
    const int warpN = warp & 3;     // 0..3

    const int lrow = tid & 127;
    const int lcc  = (tid >> 7) * 16;   // half offset: 0 or 16

    const __half* Ap  = A + (size_t)(bm0 + lrow) * 1024;
    const __half* Wp0 = W + (size_t)(bn0 + lrow) * 1024;
    const __half* Wp1 = Wp0 + (size_t)128 * 1024;

    #pragma unroll
    for (int s = 0; s < NSTG - 1; s++) {
        int ko = s * 32 + lcc;
        cpasync16(&sA[s][lrow][lcc],           Ap  + ko);
        cpasync16(&sA[s][lrow][lcc + 8],       Ap  + ko + 8);
        cpasync16(&sB[s][lrow][lcc],           Wp0 + ko);
        cpasync16(&sB[s][lrow][lcc + 8],       Wp0 + ko + 8);
        cpasync16(&sB[s][lrow + 128][lcc],     Wp1 + ko);
        cpasync16(&sB[s][lrow + 128][lcc + 8], Wp1 + ko + 8);
        cp_commit();
    }

    float acc[4][8][4];
    #pragma unroll
    for (int mt = 0; mt < 4; mt++)
        #pragma unroll
        for (int nt = 0; nt < 8; nt++)
            #pragma unroll
            for (int i = 0; i < 4; i++) acc[mt][nt][i] = 0.0f;

    for (int kt = 0; kt < 32; kt++) {
        const int s = kt % NSTG;
        cp_wait<NSTG - 2>();
        __syncthreads();

        if (kt + NSTG - 1 < 32) {
            const int sn = (kt + NSTG - 1) % NSTG;
            const int ko = (kt + NSTG - 1) * 32 + lcc;
            cpasync16(&sA[sn][lrow][lcc],           Ap  + ko);
            cpasync16(&sA[sn][lrow][lcc + 8],       Ap  + ko + 8);
            cpasync16(&sB[sn][lrow][lcc],           Wp0 + ko);
            cpasync16(&sB[sn][lrow][lcc + 8],       Wp0 + ko + 8);
            cpasync16(&sB[sn][lrow + 128][lcc],     Wp1 + ko);
            cpasync16(&sB[sn][lrow + 128][lcc + 8], Wp1 + ko + 8);
        }
        cp_commit();

        uint4 Bf[8];
        #pragma unroll
        for (int nt = 0; nt < 8; nt++)
            Bf[nt] = *(const uint4*)&sB[s][warpN * 64 + nt * 8 + g][8 * q];

        #pragma unroll
        for (int mt = 0; mt < 4; mt++) {
            int r = warpM * 64 + mt * 16 + g;
            uint4 lo = *(const uint4*)&sA[s][r][8 * q];
            uint4 hi = *(const uint4*)&sA[s][r + 8][8 * q];
            #pragma unroll
            for (int nt = 0; nt < 8; nt++) {
                mma_f16(acc[mt][nt][0], acc[mt][nt][1], acc[mt][nt][2], acc[mt][nt][3],
                        lo.x, hi.x, lo.y, hi.y, Bf[nt].x, Bf[nt].y);
                mma_f16(acc[mt][nt][0], acc[mt][nt][1], acc[mt][nt][2], acc[mt][nt][3],
                        lo.z, hi.z, lo.w, hi.w, Bf[nt].z, Bf[nt].w);
            }
        }
    }

    #pragma unroll
    for (int mt = 0; mt < 4; mt++) {
        #pragma unroll
        for (int nt = 0; nt < 8; nt++) {
            int col = bn0 + warpN * 64 + nt * 8 + 2 * q;
            float b0 = bias[col] * bias_scale, b1 = bias[col + 1] * bias_scale;
            #pragma unroll
            for (int half = 0; half < 2; half++) {
                int row = bm0 + warpM * 64 + mt * 16 + g + half * 8;
                float vx = acc[mt][nt][half * 2 + 0] + b0;
                float vy = acc[mt][nt][half * 2 + 1] + b1;
                if (out_mode == 0) {
                    float2 v = make_float2(vx, vy);
                    *(float2*)&outf[(size_t)row * HID + col] = v;
                } else {
                    int bb = row >> 11, ss = row & 2047;
                    int hh = col >> 6, dd = col & 63;
                    if (out_mode == 1) {
                        int np = perm32_pair(dd & 31);
                        size_t idx = (((size_t)bb * NH + hh) * SS + ss) * DK
                                     + (dd & ~31) + np;
                        *(unsigned*)&outh[idx] = packh2(vx, vy);
                    } else {
                        int ps = (ss & ~31) + perm32(ss & 31);
                        size_t base = ((size_t)bb * NH + hh) * DK;
                        outh[(base + dd) * SS + ps]     = __float2half_rn(vx);
                        outh[(base + dd + 1) * SS + ps] = __float2half_rn(vy);
                    }
                }
            }
        }
    }
}

__global__ void __launch_bounds__(256)
qkv_gemm(const float* __restrict__ bq,
         const float* __restrict__ bk,
         const float* __restrict__ bv)
{
    extern __shared__ __half smh[];
    const int z = blockIdx.z;
    const __half* A = (z == 0) ? c_q  : (z == 1) ? c_k  : c_v;
    const __half* W = (z == 0) ? c_wq : (z == 1) ? c_wk : c_wv;
    const float* bb = (z == 0) ? bq   : (z == 1) ? bk   : bv;
    __half* out     = (z == 0) ? g_q  : (z == 1) ? g_k  : g_v;
    float bsc       = (z == 0) ? 0.125f : 1.0f;
    int mode        = (z == 2) ? 2 : 1;
    gemm_core(A, W, bb, bsc, nullptr, out, mode, smh,
              blockIdx.y * GBM, blockIdx.x * GBN);
}

__global__ void __launch_bounds__(256)
out_gemm(const float* __restrict__ bo, float* __restrict__ out)
{
    extern __shared__ __half smh[];
    gemm_core(g_x, c_wo, bo, 1.0f, out, nullptr, 0, smh,
              blockIdx.y * GBM, blockIdx.x * GBN);
}

// ---------------------------------------------------------------------------
// Flash attention, fp16 mma m16n8k16. Br=256 (8 warps x m32), Bc=64.
// Smem rows = 64 halves (128B) with 64B XOR swizzle (chunk ^ (row&1)*4).
// Q[256], K[2][64], V[2][64 d-rows], P[256], mask[2048 floats].
// ---------------------------------------------------------------------------
#define ATT_SMEM ((256*64 + 2*64*64 + 2*64*64 + 256*64) * 2 + SS * 4)  // 104 KB

__global__ void __launch_bounds__(256)
attn_f16(const int* __restrict__ mask)
{
    extern __shared__ __half smh[];
    __half* Qs = smh;                    // [256][64]
    __half* Ks = Qs + 256 * 64;          // [2][64][64]
    __half* Vs = Ks + 2 * 64 * 64;       // [2][64][64]  rows = d
    __half* Ps = Vs + 2 * 64 * 64;       // [256][64]
    float* maskF = (float*)(Ps + 256 * 64);  // [2048]

    const int tid  = threadIdx.x;
    const int warp = tid >> 5;
    const int lane = tid & 31;
    const int g    = lane >> 2;
    const int q    = lane & 3;
    const int rb   = warp * 32;

    const int bh = blockIdx.y;
    const int b  = bh >> 4;
    const int h  = bh & 15;
    const int q0 = blockIdx.x * 256;

    const __half* qptr  = g_q + ((size_t)bh * SS + q0) * DK;
    const __half* kbase = g_k + (size_t)bh * SS * DK;
    const __half* vbase = g_v + (size_t)bh * DK * SS;

    // Prologue: stage Q (swizzled) + K0/V0 via cp.async
    for (int e = tid; e < 256 * 8; e += 256) {
        int r = e >> 3, c = e & 7;
        cpasync16(&Qs[r * 64 + ((c ^ ((r & 1) << 2)) << 3)], qptr + r * DK + c * 8);
    }
    for (int e = tid; e < 64 * 8; e += 256) {
        int r = e >> 3, c = e & 7;
        cpasync16(&Ks[r * 64 + ((c ^ ((r & 1) << 2)) << 3)], kbase + (size_t)r * DK + c * 8);
        cpasync16(&Vs[r * 64 + ((c ^ ((r & 1) << 2)) << 3)], vbase + (size_t)r * SS + c * 8);
    }
    cp_commit();

    for (int i = tid; i < SS; i += 256)
        maskF[i] = (mask[b * SS + i] == 0) ? 0.0f : 1.0f;

    float o[2][8][4];
    #pragma unroll
    for (int f = 0; f < 2; f++)
        #pragma unroll
        for (int nt = 0; nt < 8; nt++)
            #pragma unroll
            for (int i = 0; i < 4; i++) o[f][nt][i] = 0.0f;
    float mrow[4] = {-1e30f, -1e30f, -1e30f, -1e30f};
    float lrow[4] = {0.0f, 0.0f, 0.0f, 0.0f};

    for (int kt = 0; kt < SS / 64; kt++) {
        const int buf = kt & 1;

        if (kt + 1 < SS / 64) {
            const __half* kp = kbase + (size_t)(kt + 1) * 64 * DK;
            for (int e = tid; e < 64 * 8; e += 256) {
                int r = e >> 3, c = e & 7;
                int sw = (c ^ ((r & 1) << 2)) << 3;
                cpasync16(&Ks[(buf ^ 1) * 4096 + r * 64 + sw], kp + (size_t)r * DK + c * 8);
                cpasync16(&Vs[(buf ^ 1) * 4096 + r * 64 + sw],
                          vbase + (size_t)r * SS + (kt + 1) * 64 + c * 8);
            }
        }
        cp_commit();
        cp_wait<1>();
        __syncthreads();

        const __half* Kb = Ks + buf * 4096;
        const __half* Vb = Vs + buf * 4096;

        // ---- S = Q K^T ----
        float s[2][8][4];
        #pragma unroll
        for (int f = 0; f < 2; f++)
            #pragma unroll
            for (int nt = 0; nt < 8; nt++)
                #pragma unroll
                for (int i = 0; i < 4; i++) s[f][nt][i] = 0.0f;

        #pragma unroll
        for (int kb = 0; kb < 2; kb++) {
            uint4 aQ[2][2];
            #pragma unroll
            for (int f = 0; f < 2; f++) {
                int r0 = rb + f * 16 + g;
                int sw = (((kb << 2) + q) ^ ((r0 & 1) << 2)) << 3;
                aQ[f][0] = *(const uint4*)&Qs[r0 * 64 + sw];
                aQ[f][1] = *(const uint4*)&Qs[(r0 + 8) * 64 + sw];
            }
            #pragma unroll
            for (int nt = 0; nt < 8; nt++) {
                int c = nt * 8 + g;
                uint4 bK = *(const uint4*)&Kb[c * 64 + ((((kb << 2) + q) ^ ((c & 1) << 2)) << 3)];
                #pragma unroll
                for (int f = 0; f < 2; f++) {
                    mma_f16(s[f][nt][0], s[f][nt][1], s[f][nt][2], s[f][nt][3],
                            aQ[f][0].x, aQ[f][1].x, aQ[f][0].y, aQ[f][1].y, bK.x, bK.y);
                    mma_f16(s[f][nt][0], s[f][nt][1], s[f][nt][2], s[f][nt][3],
                            aQ[f][0].z, aQ[f][1].z, aQ[f][0].w, aQ[f][1].w, bK.z, bK.w);
                }
            }
        }

        // ---- mask ----
        #pragma unroll
        for (int nt = 0; nt < 8; nt++) {
            float mk0 = maskF[kt * 64 + nt * 8 + 2 * q];
            float mk1 = maskF[kt * 64 + nt * 8 + 2 * q + 1];
            #pragma unroll
            for (int f = 0; f < 2; f++) {
                s[f][nt][0] = (mk0 == 0.0f) ? -10000.0f : s[f][nt][0];
                s[f][nt][2] = (mk0 == 0.0f) ? -10000.0f : s[f][nt][2];
                s[f][nt][1] = (mk1 == 0.0f) ? -10000.0f : s[f][nt][1];
                s[f][nt][3] = (mk1 == 0.0f) ? -10000.0f : s[f][nt][3];
            }
        }

        // ---- online softmax ----
        #pragma unroll
        for (int f = 0; f < 2; f++) {
            #pragma unroll
            for (int half = 0; half < 2; half++) {
                int ri = f * 2 + half;
                float mx = -1e30f;
                #pragma unroll
                for (int nt = 0; nt < 8; nt++) {
                    mx = fmaxf(mx, s[f][nt][half * 2 + 0]);
                    mx = fmaxf(mx, s[f][nt][half * 2 + 1]);
                }
                mx = fmaxf(mx, __shfl_xor_sync(0xffffffffu, mx, 1));
                mx = fmaxf(mx, __shfl_xor_sync(0xffffffffu, mx, 2));
                float mnew  = fmaxf(mrow[ri], mx);
                float alpha = __expf(mrow[ri] - mnew);
                float rs = 0.0f;
                #pragma unroll
                for (int nt = 0; nt < 8; nt++) {
                    float p0 = __expf(s[f][nt][half * 2 + 0] - mnew);
                    float p1 = __expf(s[f][nt][half * 2 + 1] - mnew);
                    s[f][nt][half * 2 + 0] = p0;
                    s[f][nt][half * 2 + 1] = p1;
                    rs += p0 + p1;
                }
                rs += __shfl_xor_sync(0xffffffffu, rs, 1);
                rs += __shfl_xor_sync(0xffffffffu, rs, 2);
                lrow[ri] = lrow[ri] * alpha + rs;
                mrow[ri] = mnew;
                #pragma unroll
                for (int nt = 0; nt < 8; nt++) {
                    o[f][nt][half * 2 + 0] *= alpha;
                    o[f][nt][half * 2 + 1] *= alpha;
                }
            }
        }

        // ---- stage P (fp16, permuted A layout, 2x STS.128 per row) ----
        #pragma unroll
        for (int f = 0; f < 2; f++) {
            #pragma unroll
            for (int rh = 0; rh < 2; rh++) {
                int row = rb + f * 16 + g + rh * 8;
                uint4 u0, u1;
                u0.x = packh2(s[f][0][rh * 2], s[f][0][rh * 2 + 1]);
                u0.y = packh2(s[f][1][rh * 2], s[f][1][rh * 2 + 1]);
                u0.z = packh2(s[f][2][rh * 2], s[f][2][rh * 2 + 1]);
                u0.w = packh2(s[f][3][rh * 2], s[f][3][rh * 2 + 1]);
                u1.x = packh2(s[f][4][rh * 2], s[f][4][rh * 2 + 1]);
                u1.y = packh2(s[f][5][rh * 2], s[f][5][rh * 2 + 1]);
                u1.z = packh2(s[f][6][rh * 2], s[f][6][rh * 2 + 1]);
                u1.w = packh2(s[f][7][rh * 2], s[f][7][rh * 2 + 1]);
                int sw = (row & 1) << 2;
                *(uint4*)&Ps[row * 64 + ((q ^ sw) << 3)]       = u0;
                *(uint4*)&Ps[row * 64 + (((4 + q) ^ sw) << 3)] = u1;
            }
        }
        __syncthreads();

        // ---- O += P V ----
        #pragma unroll
        for (int cb = 0; cb < 2; cb++) {
            uint4 aP[2][2];
            #pragma unroll
            for (int f = 0; f < 2; f++) {
                int r0 = rb + f * 16 + g;
                int sw = (((cb << 2) + q) ^ ((r0 & 1) << 2)) << 3;
                aP[f][0] = *(const uint4*)&Ps[r0 * 64 + sw];
                aP[f][1] = *(const uint4*)&Ps[(r0 + 8) * 64 + sw];
            }
            #pragma unroll
            for (int nt = 0; nt < 8; nt++) {
                int d = nt * 8 + g;
                uint4 bV = *(const uint4*)&Vb[d * 64 + ((((cb << 2) + q) ^ ((d & 1) << 2)) << 3)];
                #pragma unroll
                for (int f = 0; f < 2; f++) {
                    mma_f16(o[f][nt][0], o[f][nt][1], o[f][nt][2], o[f][nt][3],
                            aP[f][0].x, aP[f][1].x, aP[f][0].y, aP[f][1].y, bV.x, bV.y);
                    mma_f16(o[f][nt][0], o[f][nt][1], o[f][nt][2], o[f][nt][3],
                            aP[f][0].z, aP[f][1].z, aP[f][0].w, aP[f][1].w, bV.z, bV.w);
                }
            }
        }
        __syncthreads();
    }

    // Epilogue: normalize, fp16-round, write g_x [b,s,hid-perm]
    #pragma unroll
    for (int f = 0; f < 2; f++) {
        float inv0 = 1.0f / lrow[f * 2 + 0];
        float inv1 = 1.0f / lrow[f * 2 + 1];
        #pragma unroll
        for (int nt = 0; nt < 8; nt++) {
            int np   = 8 * q + 4 * ((nt & 3) >> 1) + 2 * (nt & 1);
            int dpos = h * DK + ((nt >= 4) ? 32 : 0) + np;
            int rowA = q0 + rb + f * 16 + g;
            int rowB = rowA + 8;
            *(unsigned*)&g_x[((size_t)b * SS + rowA) * HID + dpos] =
                packh2(o[f][nt][0] * inv0, o[f][nt][1] * inv0);
            *(unsigned*)&g_x[((size_t)b * SS + rowB) * HID + dpos] =
                packh2(o[f][nt][2] * inv1, o[f][nt][3] * inv1);
        }
    }
}

// ---------------------------------------------------------------------------
extern "C" void kernel_launch(void* const* d_in, const int* in_sizes, int n_in,
                              void* d_out, int out_size)
{
    const float* query = (const float*)d_in[0];
    const float* key   = (const float*)d_in[1];
    const float* value = (const float*)d_in[2];
    const float* bias  = (const float*)d_in[3];
    const int*   mask  = (const int*)d_in[4];
    const float* wq = (const float*)d_in[5];
    const float* bq = (const float*)d_in[6];
    const float* wk = (const float*)d_in[7];
    const float* bk = (const float*)d_in[8];
    const float* wv = (const float*)d_in[9];
    const float* bv = (const float*)d_in[10];
    const float* wo = (const float*)d_in[11];
    const float* bo = (const float*)d_in[12];
    float* out = (float*)d_out;

    cudaFuncSetAttribute(attn_f16,
                         cudaFuncAttributeMaxDynamicSharedMemorySize, ATT_SMEM);
    cudaFuncSetAttribute(qkv_gemm,
                         cudaFuncAttributeMaxDynamicSharedMemorySize, GEMM_SMEM);
    cudaFuncSetAttribute(out_gemm,
                         cudaFuncAttributeMaxDynamicSharedMemorySize, GEMM_SMEM);

    prep_kernel<<<dim3(4096, 7), 256>>>(query, key, value, bias, wq, wk, wv, wo);
    qkv_gemm<<<dim3(HID / GBN, MM / GBM, 3), 256, GEMM_SMEM>>>(bq, bk, bv);
    attn_f16<<<dim3(SS / 256, BB * NH), 256, ATT_SMEM>>>(mask);
    out_gemm<<<dim3(HID / GBN, MM / GBM), 256, GEMM_SMEM>>>(bo, out);
}